// round 4
// baseline (speedup 1.0000x reference)
#include <cuda_runtime.h>
#include <math.h>

// ---------------- scratch (device globals; no allocations) ----------------
__device__ float g_P[134217728];   // pre-pool conv output (max 512x128x128x16 NHWC)
__device__ float g_X[33554432];    // stage state (NHWC)
__device__ float g_O[33554432];    // resblock temp (NHWC)
__device__ float g_ca[512 * 32];
__device__ float g_sp[512 * 2 * 256];
__device__ float g_feat[512 * 256];
__device__ float g_gi[512 * 384];
__device__ float g_hid[512 * 128];
__device__ float g_fcwT[256 * 8192];  // fc_w permuted to NHWC-k order

__device__ __forceinline__ float sigf(float x) { return 1.0f / (1.0f + expf(-x)); }

__device__ __forceinline__ unsigned tf32u(float x) {
    unsigned r;
    asm("cvt.rna.tf32.f32 %0, %1;" : "=r"(r) : "f"(x));
    return r;
}
__device__ __forceinline__ float tf32f(float x) { return __uint_as_float(tf32u(x)); }

__device__ __forceinline__ void mma8(float* c, unsigned a0, unsigned a1, unsigned a2, unsigned a3,
                                     float b0f, float b1f) {
    unsigned b0 = __float_as_uint(b0f), b1 = __float_as_uint(b1f);
    asm volatile(
        "mma.sync.aligned.m16n8k8.row.col.f32.tf32.tf32.f32 "
        "{%0,%1,%2,%3},{%4,%5,%6,%7},{%8,%9},{%0,%1,%2,%3};"
        : "+f"(c[0]), "+f"(c[1]), "+f"(c[2]), "+f"(c[3])
        : "r"(a0), "r"(a1), "r"(a2), "r"(a3), "r"(b0), "r"(b1));
}
#define U(x) __float_as_uint(x)

// k-slot permutations: contiguous float4/float2 per lane covers k = t, t+4, t+8, t+12
__device__ __forceinline__ int slot8(int k)  { return 2 * (k & 3) + (k >> 2); }
__device__ __forceinline__ int slot16(int k) { return 4 * (k & 3) + (k >> 2); }
__device__ __forceinline__ int slot32(int k) { return 4 * (k & 3) + ((k >> 2) & 3) + ((k >> 4) << 4); }

// ---------------- 3x3 conv pad=1 via tf32 MMA, wide-LDS fragments ----------
// Block 256 thr (8 warps). Tile = (8*RPW) rows x 16 cols. Warp: RPW M-tiles of
// 16 pixels (one tile row each). smem A: halo (8*RPW+2)x18 pixel rows, CINP
// floats each in permuted slot order; CIN=32 adds parity-XOR bank swizzle.
template <int CIN, int COUT, int RPW, bool RELU_IN, bool RESID, bool RELU_OUT, bool NCHW>
__global__ __launch_bounds__(256) void conv_mma_kernel(
    const float* __restrict__ in, const float* __restrict__ w,
    const float* __restrict__ bias, float* __restrict__ out,
    const float* __restrict__ resid, int H, int W) {
    constexpr int CINP = (CIN <= 8) ? 8 : ((CIN <= 16) ? 16 : 32);
    constexpr int NB = COUT / 8;
    constexpr int TH = 8 * RPW;
    constexpr int HALO = TH + 2;
    constexpr int A_SZ = HALO * 18 * CINP;
    constexpr int W_SZ = 9 * COUT * CINP;

    extern __shared__ float sm[];
    float* s_in = sm;
    float* s_w = sm + A_SZ;

    const int tid = threadIdx.x;
    const int n = blockIdx.z;
    const int by = blockIdx.y * TH, bx = blockIdx.x * 16;

    for (int i = tid; i < A_SZ + W_SZ; i += 256) sm[i] = 0.0f;
    __syncthreads();

    // weights: global OIHW -> smem [tap][co][slot(ci)]
    for (int i = tid; i < COUT * CIN * 9; i += 256) {
        int co = i / (CIN * 9);
        int r = i - co * CIN * 9;
        int ci = r / 9;
        int tap = r - ci * 9;
        int sl = (CINP == 8) ? slot8(ci) : (CINP == 16) ? slot16(ci) : slot32(ci);
        if (CINP == 32) sl ^= (co & 1) << 4;
        s_w[(tap * COUT + co) * CINP + sl] = tf32f(w[i]);
    }
    // input halo tile
    for (int i = tid; i < HALO * 18 * CIN; i += 256) {
        int pix, ci;
        if (NCHW) { ci = i / (HALO * 18); pix = i - ci * HALO * 18; }
        else      { pix = i / CIN; ci = i - pix * CIN; }
        int iy = pix / 18, ix = pix - iy * 18;
        int gy = by + iy - 1, gx = bx + ix - 1;
        if (gy >= 0 && gy < H && gx >= 0 && gx < W) {
            float v = NCHW ? in[((long)(n * CIN + ci) * H + gy) * W + gx]
                           : in[((long)(n * H + gy) * W + gx) * CIN + ci];
            if (RELU_IN) v = fmaxf(v, 0.0f);
            int sl = (CINP == 8) ? slot8(ci) : (CINP == 16) ? slot16(ci) : slot32(ci);
            if (CINP == 32) sl ^= (pix & 1) << 4;
            s_in[pix * CINP + sl] = tf32f(v);
        }
    }
    __syncthreads();

    const int warp = tid >> 5, lane = tid & 31, g = lane >> 2, t = lane & 3;
    const int wr0 = warp * RPW;

    float acc[RPW][NB][4];
#pragma unroll
    for (int r = 0; r < RPW; r++)
#pragma unroll
        for (int nb = 0; nb < NB; nb++)
#pragma unroll
            for (int q = 0; q < 4; q++) acc[r][nb][q] = 0.0f;

#pragma unroll
    for (int tap = 0; tap < 9; tap++) {
        const int dy = tap / 3 - 1, dx = tap % 3 - 1;
        if (CINP == 8) {
            float2 vb[NB];
#pragma unroll
            for (int nb = 0; nb < NB; nb++)
                vb[nb] = *(const float2*)(s_w + (tap * COUT + nb * 8 + g) * 8 + 2 * t);
#pragma unroll
            for (int r = 0; r < RPW; r++) {
                int prow = (wr0 + r + dy + 1) * 18 + dx + 1;
                float2 va0 = *(const float2*)(s_in + (prow + g) * 8 + 2 * t);
                float2 va1 = *(const float2*)(s_in + (prow + g + 8) * 8 + 2 * t);
#pragma unroll
                for (int nb = 0; nb < NB; nb++)
                    mma8(acc[r][nb], U(va0.x), U(va1.x), U(va0.y), U(va1.y), vb[nb].x, vb[nb].y);
            }
        } else if (CINP == 16) {
            float4 vb[NB];
#pragma unroll
            for (int nb = 0; nb < NB; nb++)
                vb[nb] = *(const float4*)(s_w + (tap * COUT + nb * 8 + g) * 16 + 4 * t);
#pragma unroll
            for (int r = 0; r < RPW; r++) {
                int prow = (wr0 + r + dy + 1) * 18 + dx + 1;
                float4 va0 = *(const float4*)(s_in + (prow + g) * 16 + 4 * t);
                float4 va1 = *(const float4*)(s_in + (prow + g + 8) * 16 + 4 * t);
#pragma unroll
                for (int nb = 0; nb < NB; nb++) {
                    mma8(acc[r][nb], U(va0.x), U(va1.x), U(va0.y), U(va1.y), vb[nb].x, vb[nb].y);
                    mma8(acc[r][nb], U(va0.z), U(va1.z), U(va0.w), U(va1.w), vb[nb].z, vb[nb].w);
                }
            }
        } else {  // CINP == 32, parity-XOR swizzle
            const int pb = (g & 1) << 4;
            float4 vbl[NB], vbh[NB];
#pragma unroll
            for (int nb = 0; nb < NB; nb++) {
                const float* wb = s_w + (tap * COUT + nb * 8 + g) * 32 + 4 * t;
                vbl[nb] = *(const float4*)(wb + pb);
                vbh[nb] = *(const float4*)(wb + (16 - pb));
            }
            const int pa = ((g + dx + 1) & 1) << 4;  // parity of smem pixel row (18*even)
#pragma unroll
            for (int r = 0; r < RPW; r++) {
                int prow = (wr0 + r + dy + 1) * 18 + dx + 1;
                const float* a0p = s_in + (prow + g) * 32 + 4 * t;
                const float* a1p = s_in + (prow + g + 8) * 32 + 4 * t;
                float4 v0l = *(const float4*)(a0p + pa);
                float4 v0h = *(const float4*)(a0p + (16 - pa));
                float4 v1l = *(const float4*)(a1p + pa);
                float4 v1h = *(const float4*)(a1p + (16 - pa));
#pragma unroll
                for (int nb = 0; nb < NB; nb++) {
                    mma8(acc[r][nb], U(v0l.x), U(v1l.x), U(v0l.y), U(v1l.y), vbl[nb].x, vbl[nb].y);
                    mma8(acc[r][nb], U(v0l.z), U(v1l.z), U(v0l.w), U(v1l.w), vbl[nb].z, vbl[nb].w);
                    mma8(acc[r][nb], U(v0h.x), U(v1h.x), U(v0h.y), U(v1h.y), vbh[nb].x, vbh[nb].y);
                    mma8(acc[r][nb], U(v0h.z), U(v1h.z), U(v0h.w), U(v1h.w), vbh[nb].z, vbh[nb].w);
                }
            }
        }
    }

    // epilogue: bias (+resid) (+relu), NHWC float2 stores
#pragma unroll
    for (int r = 0; r < RPW; r++) {
        int oy = by + wr0 + r;
        long rowbase = (long)(n * H + oy) * W;
#pragma unroll
        for (int nb = 0; nb < NB; nb++) {
            int co = nb * 8 + 2 * t;
            float bv0 = bias[co], bv1 = bias[co + 1];
            long i0 = (rowbase + bx + g) * COUT + co;
            long i1 = (rowbase + bx + g + 8) * COUT + co;
            float2 v0 = make_float2(acc[r][nb][0] + bv0, acc[r][nb][1] + bv1);
            float2 v1 = make_float2(acc[r][nb][2] + bv0, acc[r][nb][3] + bv1);
            if (RESID) {
                float2 r0 = *(const float2*)(resid + i0);
                float2 r1 = *(const float2*)(resid + i1);
                v0.x += r0.x; v0.y += r0.y; v1.x += r1.x; v1.y += r1.y;
            }
            if (RELU_OUT) {
                v0.x = fmaxf(v0.x, 0.0f); v0.y = fmaxf(v0.y, 0.0f);
                v1.x = fmaxf(v1.x, 0.0f); v1.y = fmaxf(v1.y, 0.0f);
            }
            *(float2*)(out + i0) = v0;
            *(float2*)(out + i1) = v1;
        }
    }
}

// ---------------- maxpool 3x3 s2 p1, NHWC ----------------
__global__ void maxpool_nhwc(const float* __restrict__ in, float* __restrict__ out,
                             int C, int H, int W) {
    int H2 = H >> 1, W2 = W >> 1;
    long total = (long)512 * H2 * W2 * C;
    long i = (long)blockIdx.x * blockDim.x + threadIdx.x;
    if (i >= total) return;
    int c = (int)(i % C); long r = i / C;
    int ox = (int)(r % W2); r /= W2;
    int oy = (int)(r % H2); int n = (int)(r / H2);
    float m = -3.4e38f;
    int y0 = oy * 2 - 1, x0 = ox * 2 - 1;
#pragma unroll
    for (int dy = 0; dy < 3; dy++) {
        int y = y0 + dy;
        if (y < 0 || y >= H) continue;
#pragma unroll
        for (int dx = 0; dx < 3; dx++) {
            int x = x0 + dx;
            if (x < 0 || x >= W) continue;
            m = fmaxf(m, in[((long)(n * H + y) * W + x) * C + c]);
        }
    }
    out[i] = m;
}

// ---------------- CBAM ----------------
__global__ void cbam_ca_nhwc(const float* __restrict__ x, const float* __restrict__ fc1,
                             const float* __restrict__ fc2, float* __restrict__ ca) {
    int n = blockIdx.x, tid = threadIdx.x;
    int g = tid >> 5, c = tid & 31;
    __shared__ float rs[8][32], rm[8][32], s_mean[32], s_max[32], s_h[8];
    float sm = 0.0f, mx = -3.4e38f;
    for (int p = g; p < 256; p += 8) {
        float v = x[((long)n * 256 + p) * 32 + c];
        sm += v; mx = fmaxf(mx, v);
    }
    rs[g][c] = sm; rm[g][c] = mx;
    __syncthreads();
    if (tid < 32) {
        float s = 0.0f, m = -3.4e38f;
        for (int q = 0; q < 8; q++) { s += rs[q][tid]; m = fmaxf(m, rm[q][tid]); }
        s_mean[tid] = s * (1.0f / 256.0f); s_max[tid] = m;
    }
    __syncthreads();
    if (tid < 8) {
        float hm = 0.0f, hx = 0.0f;
        for (int k = 0; k < 32; k++) {
            float wv = fc1[tid * 32 + k];
            hm += s_mean[k] * wv; hx += s_max[k] * wv;
        }
        s_h[tid] = fmaxf(hm, 0.0f) + fmaxf(hx, 0.0f);
    }
    __syncthreads();
    if (tid < 32) {
        float o = 0.0f;
        for (int j = 0; j < 8; j++) o += s_h[j] * fc2[tid * 8 + j];
        ca[n * 32 + tid] = sigf(o);
    }
}

__global__ void cbam_apply_nhwc(float* x, const float* __restrict__ ca, float* __restrict__ sp) {
    int n = blockIdx.x, p = threadIdx.x;
    __shared__ float s_ca[32];
    if (p < 32) s_ca[p] = ca[n * 32 + p];
    __syncthreads();
    float* base = x + ((long)n * 256 + p) * 32;
    float sum = 0.0f, mx = -3.4e38f;
#pragma unroll
    for (int c = 0; c < 32; c++) {
        float v = base[c] * s_ca[c];
        base[c] = v;
        sum += v; mx = fmaxf(mx, v);
    }
    sp[(long)n * 512 + p] = sum * (1.0f / 32.0f);
    sp[(long)n * 512 + 256 + p] = mx;
}

__global__ void cbam_sa_nhwc(float* x, const float* __restrict__ sp, const float* __restrict__ spw) {
    int n = blockIdx.x, p = threadIdx.x;
    int oy = p >> 4, ox = p & 15;
    __shared__ float s_sp[512], s_w[98];
    s_sp[p] = sp[(long)n * 512 + p];
    s_sp[256 + p] = sp[(long)n * 512 + 256 + p];
    if (p < 98) s_w[p] = spw[p];
    __syncthreads();
    float a = 0.0f;
#pragma unroll
    for (int ci = 0; ci < 2; ci++)
        for (int ky = 0; ky < 7; ky++) {
            int y = oy + ky - 3;
            if (y < 0 || y >= 16) continue;
            for (int kx = 0; kx < 7; kx++) {
                int xx = ox + kx - 3;
                if (xx < 0 || xx >= 16) continue;
                a = fmaf(s_sp[ci * 256 + y * 16 + xx], s_w[(ci * 7 + ky) * 7 + kx], a);
            }
        }
    float sa = sigf(a);
    float* base = x + ((long)n * 256 + p) * 32;
#pragma unroll
    for (int c = 0; c < 32; c++) base[c] *= sa;
}

// permute fc_w[n][c*256+p] -> g_fcwT[n][p*32+c] (matches NHWC flatten)
__global__ void fcw_permute(const float* __restrict__ w, float* __restrict__ wt) {
    int i = blockIdx.x * 256 + threadIdx.x;
    if (i >= 256 * 8192) return;
    int n = i >> 13;
    int r = i & 8191;
    int c = r >> 8, p = r & 255;
    wt[(n << 13) + p * 32 + c] = w[i];
}

// ---------------- GEMM: C[M,N] = A[M,K] @ B[N,K]^T + bias, opt relu ------
__global__ void gemm_bt_kernel(const float* __restrict__ A, const float* __restrict__ B,
                               const float* __restrict__ bias, float* __restrict__ C,
                               int M, int N, int K, int relu) {
    __shared__ float sA[32 * 33];
    __shared__ float sB[32 * 33];
    int bm = blockIdx.y * 32, bn = blockIdx.x * 32;
    int tid = threadIdx.x;
    int tr = tid >> 4, tc = tid & 15;
    float acc00 = 0, acc01 = 0, acc10 = 0, acc11 = 0;
    for (int k0 = 0; k0 < K; k0 += 32) {
        for (int i = tid; i < 32 * 32; i += 256) {
            int r = i >> 5, c = i & 31;
            sA[r * 33 + c] = (bm + r < M) ? A[(long)(bm + r) * K + k0 + c] : 0.0f;
            sB[r * 33 + c] = (bn + r < N) ? B[(long)(bn + r) * K + k0 + c] : 0.0f;
        }
        __syncthreads();
#pragma unroll
        for (int k = 0; k < 32; k++) {
            float a0 = sA[(tr * 2) * 33 + k], a1 = sA[(tr * 2 + 1) * 33 + k];
            float b0 = sB[(tc * 2) * 33 + k], b1 = sB[(tc * 2 + 1) * 33 + k];
            acc00 = fmaf(a0, b0, acc00); acc01 = fmaf(a0, b1, acc01);
            acc10 = fmaf(a1, b0, acc10); acc11 = fmaf(a1, b1, acc11);
        }
        __syncthreads();
    }
    float accs[2][2] = {{acc00, acc01}, {acc10, acc11}};
#pragma unroll
    for (int r = 0; r < 2; r++)
#pragma unroll
        for (int c = 0; c < 2; c++) {
            int m = bm + tr * 2 + r, nn = bn + tc * 2 + c;
            if (m < M && nn < N) {
                float v = accs[r][c] + bias[nn];
                if (relu) v = fmaxf(v, 0.0f);
                C[(long)m * N + nn] = v;
            }
        }
}

// ---------------- GRU scan ----------------
__global__ void gru_scan_kernel(const float* __restrict__ gi, const float* __restrict__ done,
                                const float* __restrict__ h0, const float* __restrict__ whh,
                                const float* __restrict__ bhh, float* __restrict__ hidden) {
    extern __shared__ float sm[];
    float* s_whh = sm;
    float* s_gh = sm + 128 * 384;
    float* s_h = s_gh + 384;
    float* s_hm = s_h + 128;
    int b = blockIdx.x, j = threadIdx.x;

    for (int i = j; i < 384 * 128; i += 384) {
        int jj = i >> 7, k = i & 127;
        s_whh[k * 384 + jj] = whh[i];
    }
    if (j < 128) s_h[j] = h0[b * 128 + j];
    __syncthreads();

    float bh = bhh[j];
    for (int t = 0; t < 64; t++) {
        float dt = done[t * 8 + b];
        if (j < 128) s_hm[j] = (1.0f - dt) * s_h[j];
        __syncthreads();
        float acc = bh;
#pragma unroll 8
        for (int k = 0; k < 128; k++) acc = fmaf(s_hm[k], s_whh[k * 384 + j], acc);
        s_gh[j] = acc;
        __syncthreads();
        if (j < 128) {
            const float* gr = gi + (long)(t * 8 + b) * 384;
            float r = sigf(gr[j] + s_gh[j]);
            float z = sigf(gr[128 + j] + s_gh[128 + j]);
            float nn = tanhf(gr[256 + j] + r * s_gh[256 + j]);
            float hn = (1.0f - z) * nn + z * s_hm[j];
            s_h[j] = hn;
            hidden[(long)(t * 8 + b) * 128 + j] = hn;
        }
        __syncthreads();
    }
}

// ---------------- actor/critic heads ----------------
__global__ void heads_kernel(const float* __restrict__ hidden, const float* __restrict__ aw,
                             const float* __restrict__ ab, const float* __restrict__ cw,
                             const float* __restrict__ cb, float* __restrict__ out) {
    int row = blockIdx.x, t = threadIdx.x;
    __shared__ float s_h[128];
    s_h[t] = hidden[(long)row * 128 + t];
    __syncthreads();
    if (t < 4) {
        const float* w = (t < 3) ? (aw + t * 128) : cw;
        float s = (t < 3) ? ab[t] : cb[0];
        for (int k = 0; k < 128; k++) s = fmaf(s_h[k], w[k], s);
        out[row * 4 + t] = s;
    }
}

// ---------------- host-side launch helpers ----------------
template <int CIN, int COUT, int RPW, bool RELU_IN, bool RESID, bool RELU_OUT, bool NCHW>
static void launch_conv(const float* in, const float* w, const float* b,
                        float* out, const float* resid, int H, int W) {
    constexpr int CINP = (CIN <= 8) ? 8 : ((CIN <= 16) ? 16 : 32);
    constexpr int HALO = 8 * RPW + 2;
    int smem = (HALO * 18 * CINP + 9 * COUT * CINP) * 4;
    auto kfn = conv_mma_kernel<CIN, COUT, RPW, RELU_IN, RESID, RELU_OUT, NCHW>;
    cudaFuncSetAttribute(kfn, cudaFuncAttributeMaxDynamicSharedMemorySize, smem);
    dim3 grid(W / 16, H / (8 * RPW), 512);
    kfn<<<grid, 256, smem>>>(in, w, b, out, resid, H, W);
}

static void launch_pool(const float* in, float* out, int C, int H, int W) {
    long total = (long)512 * C * (H / 2) * (W / 2);
    maxpool_nhwc<<<(unsigned)((total + 255) / 256), 256>>>(in, out, C, H, W);
}

extern "C" void kernel_launch(void* const* d_in, const int* in_sizes, int n_in,
                              void* d_out, int out_size) {
    (void)in_sizes; (void)n_in; (void)out_size;
    const float* x        = (const float*)d_in[0];
    const float* done     = (const float*)d_in[1];
    const float* grustate = (const float*)d_in[2];
    const float* s0_cw = (const float*)d_in[3];
    const float* s0_cb = (const float*)d_in[4];
    const float* s0_rw = (const float*)d_in[5];
    const float* s0_rb = (const float*)d_in[6];
    const float* s1_cw = (const float*)d_in[7];
    const float* s1_cb = (const float*)d_in[8];
    const float* s1_rw = (const float*)d_in[9];
    const float* s1_rb = (const float*)d_in[10];
    const float* s2_cw = (const float*)d_in[11];
    const float* s2_cb = (const float*)d_in[12];
    const float* s2_rw = (const float*)d_in[13];
    const float* s2_rb = (const float*)d_in[14];
    const float* cbam_fc1 = (const float*)d_in[15];
    const float* cbam_fc2 = (const float*)d_in[16];
    const float* cbam_spw = (const float*)d_in[17];
    const float* fc_w  = (const float*)d_in[18];
    const float* fc_b  = (const float*)d_in[19];
    const float* gwih  = (const float*)d_in[20];
    const float* gwhh  = (const float*)d_in[21];
    const float* gbih  = (const float*)d_in[22];
    const float* gbhh  = (const float*)d_in[23];
    const float* aw    = (const float*)d_in[24];
    const float* ab    = (const float*)d_in[25];
    const float* cw    = (const float*)d_in[26];
    const float* cb    = (const float*)d_in[27];
    float* out = (float*)d_out;

    float *P, *X, *O, *CA, *SP, *FEAT, *GI, *HID, *FCWT;
    cudaGetSymbolAddress((void**)&P, g_P);
    cudaGetSymbolAddress((void**)&X, g_X);
    cudaGetSymbolAddress((void**)&O, g_O);
    cudaGetSymbolAddress((void**)&CA, g_ca);
    cudaGetSymbolAddress((void**)&SP, g_sp);
    cudaGetSymbolAddress((void**)&FEAT, g_feat);
    cudaGetSymbolAddress((void**)&GI, g_gi);
    cudaGetSymbolAddress((void**)&HID, g_hid);
    cudaGetSymbolAddress((void**)&FCWT, g_fcwT);

    fcw_permute<<<(256 * 8192 + 255) / 256, 256>>>(fc_w, FCWT);

    // ---- stage 0: 6->16 @128 (NCHW src) -> pool 64 -> 2 resblocks ----
    launch_conv<6, 16, 4, false, false, false, true>(x, s0_cw, s0_cb, P, nullptr, 128, 128);
    launch_pool(P, X, 16, 128, 128);
    launch_conv<16, 16, 4, true, false, false, false>(X, s0_rw + 0 * 2304, s0_rb + 0,  O, nullptr, 64, 64);
    launch_conv<16, 16, 4, true, true,  false, false>(O, s0_rw + 1 * 2304, s0_rb + 16, X, X, 64, 64);
    launch_conv<16, 16, 4, true, false, false, false>(X, s0_rw + 2 * 2304, s0_rb + 32, O, nullptr, 64, 64);
    launch_conv<16, 16, 4, true, true,  false, false>(O, s0_rw + 3 * 2304, s0_rb + 48, X, X, 64, 64);

    // ---- stage 1: 16->32 @64 -> pool 32 -> 2 resblocks ----
    launch_conv<16, 32, 2, false, false, false, false>(X, s1_cw, s1_cb, P, nullptr, 64, 64);
    launch_pool(P, X, 32, 64, 64);
    launch_conv<32, 32, 2, true, false, false, false>(X, s1_rw + 0 * 9216, s1_rb + 0,  O, nullptr, 32, 32);
    launch_conv<32, 32, 2, true, true,  false, false>(O, s1_rw + 1 * 9216, s1_rb + 32, X, X, 32, 32);
    launch_conv<32, 32, 2, true, false, false, false>(X, s1_rw + 2 * 9216, s1_rb + 64, O, nullptr, 32, 32);
    launch_conv<32, 32, 2, true, true,  false, false>(O, s1_rw + 3 * 9216, s1_rb + 96, X, X, 32, 32);

    // ---- stage 2: 32->32 @32 -> pool 16 -> 2 resblocks (last fuses final relu) ----
    launch_conv<32, 32, 2, false, false, false, false>(X, s2_cw, s2_cb, P, nullptr, 32, 32);
    launch_pool(P, X, 32, 32, 32);
    launch_conv<32, 32, 2, true, false, false, false>(X, s2_rw + 0 * 9216, s2_rb + 0,  O, nullptr, 16, 16);
    launch_conv<32, 32, 2, true, true,  false, false>(O, s2_rw + 1 * 9216, s2_rb + 32, X, X, 16, 16);
    launch_conv<32, 32, 2, true, false, false, false>(X, s2_rw + 2 * 9216, s2_rb + 64, O, nullptr, 16, 16);
    launch_conv<32, 32, 2, true, true,  true,  false>(O, s2_rw + 3 * 9216, s2_rb + 96, X, X, 16, 16);

    // ---- CBAM (NHWC) ----
    cbam_ca_nhwc<<<512, 256>>>(X, cbam_fc1, cbam_fc2, CA);
    cbam_apply_nhwc<<<512, 256>>>(X, CA, SP);
    cbam_sa_nhwc<<<512, 256>>>(X, SP, cbam_spw);

    // ---- FC 8192->256 (+relu), NHWC-k permuted weights ----
    gemm_bt_kernel<<<dim3(256 / 32, 512 / 32), 256>>>(X, FCWT, fc_b, FEAT, 512, 256, 8192, 1);

    // ---- GRU: input gates GEMM, then sequential scan ----
    gemm_bt_kernel<<<dim3(384 / 32, 512 / 32), 256>>>(FEAT, gwih, gbih, GI, 512, 384, 256, 0);
    {
        int smem = (128 * 384 + 384 + 128 + 128) * 4;
        cudaFuncSetAttribute(gru_scan_kernel, cudaFuncAttributeMaxDynamicSharedMemorySize, smem);
        gru_scan_kernel<<<8, 384, smem>>>(GI, done, grustate, gwhh, gbhh, HID);
    }

    // ---- actor / critic heads -> (512, 4) ----
    heads_kernel<<<512, 128>>>(HID, aw, ab, cw, cb, out);
}

// round 5
// speedup vs baseline: 1.5332x; 1.5332x over previous
#include <cuda_runtime.h>
#include <math.h>

// ---------------- scratch (device globals; no allocations) ----------------
__device__ float g_P[134217728];   // pre-pool conv output (max 512x128x128x16 NHWC)
__device__ float g_X[33554432];    // stage state (NHWC)
__device__ float g_O[33554432];    // resblock temp (NHWC)
__device__ float g_ca[512 * 32];
__device__ float g_sp[512 * 2 * 256];
__device__ float g_feat[512 * 256];
__device__ float g_gi[512 * 384];
__device__ float g_hid[512 * 128];
__device__ float g_fcwT[256 * 8192];   // fc_w permuted to NHWC-k order
__device__ float g_wperm[131072];      // all conv weights, tf32 [tap][co][slot(ci)]

__device__ __forceinline__ float sigf(float x) { return 1.0f / (1.0f + expf(-x)); }

__device__ __forceinline__ unsigned tf32u(float x) {
    unsigned r;
    asm("cvt.rna.tf32.f32 %0, %1;" : "=r"(r) : "f"(x));
    return r;
}
__device__ __forceinline__ float tf32f(float x) { return __uint_as_float(tf32u(x)); }

__device__ __forceinline__ void mma8(float* c, unsigned a0, unsigned a1, unsigned a2, unsigned a3,
                                     float b0f, float b1f) {
    unsigned b0 = __float_as_uint(b0f), b1 = __float_as_uint(b1f);
    asm volatile(
        "mma.sync.aligned.m16n8k8.row.col.f32.tf32.tf32.f32 "
        "{%0,%1,%2,%3},{%4,%5,%6,%7},{%8,%9},{%0,%1,%2,%3};"
        : "+f"(c[0]), "+f"(c[1]), "+f"(c[2]), "+f"(c[3])
        : "r"(a0), "r"(a1), "r"(a2), "r"(a3), "r"(b0), "r"(b1));
}
#define U(x) __float_as_uint(x)

// k-slot permutations: contiguous float2/float4 per lane covers k = t, t+4, t+8, t+12
__device__ __forceinline__ int slotp(int k, int CINP) {
    if (CINP == 8)  return 2 * (k & 3) + (k >> 2);
    if (CINP == 16) return 4 * (k & 3) + (k >> 2);
    return 4 * (k & 3) + ((k >> 2) & 3) + ((k >> 4) << 4);
}

// ---------------- weight permute prepass: OIHW -> tf32 [tap][co][slot] ----
__global__ void wperm_kernel(const float* __restrict__ src, float* __restrict__ dst,
                             int CIN, int CINP, int COUT, int nconv) {
    int total = nconv * COUT * CINP * 9;
    int i = blockIdx.x * 256 + threadIdx.x;
    if (i >= total) return;
    int tap = i % 9; int r = i / 9;
    int ci = r % CINP; r /= CINP;
    int co = r % COUT; int cv = r / COUT;
    float v = (ci < CIN) ? src[((cv * COUT + co) * CIN + ci) * 9 + tap] : 0.0f;
    dst[cv * 9 * COUT * CINP + (tap * COUT + co) * CINP + slotp(ci, CINP)] = tf32f(v);
}

// ---------------- 3x3 conv pad=1, tf32 MMA, weights from global ----------
// Block 256 thr (8 warps), 16x16 tile, 2 pixel-rows (M-tiles) per warp.
// smem: A halo tile only, 18x18 pixel rows, CINP floats (permuted slots;
// CINP=32 adds pixel-parity XOR on slot bit 4 for conflict-free LDS.128).
template <int CIN, int COUT, bool RELU_IN, bool RESID, bool RELU_OUT, bool NCHW>
__global__ __launch_bounds__(256) void conv_mma_kernel(
    const float* __restrict__ in, const float* __restrict__ wperm,
    const float* __restrict__ bias, float* __restrict__ out,
    const float* __restrict__ resid, int H, int W) {
    constexpr int CINP = (CIN <= 8) ? 8 : ((CIN <= 16) ? 16 : 32);
    constexpr int NB = COUT / 8;
    constexpr int A_SZ = 324 * CINP;   // 18*18 halo pixels

    extern __shared__ float s_in[];
    const int tid = threadIdx.x;
    const int n = blockIdx.z;
    const int by = blockIdx.y * 16, bx = blockIdx.x * 16;

    for (int i = tid; i < A_SZ; i += 256) s_in[i] = 0.0f;
    __syncthreads();

    if (NCHW) {
        for (int i = tid; i < 324 * CIN; i += 256) {
            int ci = i / 324, pix = i - ci * 324;
            int iy = pix / 18, ix = pix - iy * 18;
            int gy = by + iy - 1, gx = bx + ix - 1;
            if (gy >= 0 && gy < H && gx >= 0 && gx < W) {
                float v = in[((long)(n * CIN + ci) * H + gy) * W + gx];
                if (RELU_IN) v = fmaxf(v, 0.0f);
                int sl = slotp(ci, CINP);
                if (CINP == 32) sl ^= (pix & 1) << 4;
                s_in[pix * CINP + sl] = tf32f(v);
            }
        }
    } else {
        constexpr int C4 = CIN / 4;
        for (int i = tid; i < 324 * C4; i += 256) {
            int pix = i / C4, c4 = i - pix * C4;
            int iy = pix / 18, ix = pix - iy * 18;
            int gy = by + iy - 1, gx = bx + ix - 1;
            if (gy >= 0 && gy < H && gx >= 0 && gx < W) {
                float4 v = *(const float4*)(in + ((long)(n * H + gy) * W + gx) * CIN + 4 * c4);
                if (RELU_IN) {
                    v.x = fmaxf(v.x, 0.0f); v.y = fmaxf(v.y, 0.0f);
                    v.z = fmaxf(v.z, 0.0f); v.w = fmaxf(v.w, 0.0f);
                }
                int px = (CINP == 32) ? ((pix & 1) << 4) : 0;
                float* dst = s_in + pix * CINP;
                dst[slotp(4 * c4 + 0, CINP) ^ px] = tf32f(v.x);
                dst[slotp(4 * c4 + 1, CINP) ^ px] = tf32f(v.y);
                dst[slotp(4 * c4 + 2, CINP) ^ px] = tf32f(v.z);
                dst[slotp(4 * c4 + 3, CINP) ^ px] = tf32f(v.w);
            }
        }
    }
    __syncthreads();

    const int warp = tid >> 5, lane = tid & 31, g = lane >> 2, t = lane & 3;
    const int wr0 = warp * 2;

    float acc[2][NB][4];
#pragma unroll
    for (int r = 0; r < 2; r++)
#pragma unroll
        for (int nb = 0; nb < NB; nb++)
#pragma unroll
            for (int q = 0; q < 4; q++) acc[r][nb][q] = 0.0f;

#pragma unroll
    for (int tap = 0; tap < 9; tap++) {
        const int dy = tap / 3 - 1, dx = tap % 3 - 1;
        if (CINP == 8) {
            float2 vb[NB];
#pragma unroll
            for (int nb = 0; nb < NB; nb++)
                vb[nb] = *(const float2*)(wperm + (tap * COUT + nb * 8 + g) * 8 + 2 * t);
#pragma unroll
            for (int r = 0; r < 2; r++) {
                int prow = (wr0 + r + dy + 1) * 18 + dx + 1;
                float2 va0 = *(const float2*)(s_in + (prow + g) * 8 + 2 * t);
                float2 va1 = *(const float2*)(s_in + (prow + g + 8) * 8 + 2 * t);
#pragma unroll
                for (int nb = 0; nb < NB; nb++)
                    mma8(acc[r][nb], U(va0.x), U(va1.x), U(va0.y), U(va1.y), vb[nb].x, vb[nb].y);
            }
        } else if (CINP == 16) {
            float4 vb[NB];
#pragma unroll
            for (int nb = 0; nb < NB; nb++)
                vb[nb] = *(const float4*)(wperm + (tap * COUT + nb * 8 + g) * 16 + 4 * t);
#pragma unroll
            for (int r = 0; r < 2; r++) {
                int prow = (wr0 + r + dy + 1) * 18 + dx + 1;
                float4 va0 = *(const float4*)(s_in + (prow + g) * 16 + 4 * t);
                float4 va1 = *(const float4*)(s_in + (prow + g + 8) * 16 + 4 * t);
#pragma unroll
                for (int nb = 0; nb < NB; nb++) {
                    mma8(acc[r][nb], U(va0.x), U(va1.x), U(va0.y), U(va1.y), vb[nb].x, vb[nb].y);
                    mma8(acc[r][nb], U(va0.z), U(va1.z), U(va0.w), U(va1.w), vb[nb].z, vb[nb].w);
                }
            }
        } else {  // CINP == 32: two 16-channel halves, A parity-XOR swizzle
            const int ppar = (dx + 1 + g) & 1;
#pragma unroll
            for (int kb = 0; kb < 2; kb++) {
                float4 vb[NB];
#pragma unroll
                for (int nb = 0; nb < NB; nb++)
                    vb[nb] = *(const float4*)(wperm + (tap * COUT + nb * 8 + g) * 32 + 4 * t + 16 * kb);
                const int koff = 4 * t + (((kb ^ ppar) & 1) << 4);
#pragma unroll
                for (int r = 0; r < 2; r++) {
                    int prow = (wr0 + r + dy + 1) * 18 + dx + 1;
                    float4 va0 = *(const float4*)(s_in + (prow + g) * 32 + koff);
                    float4 va1 = *(const float4*)(s_in + (prow + g + 8) * 32 + koff);
#pragma unroll
                    for (int nb = 0; nb < NB; nb++) {
                        mma8(acc[r][nb], U(va0.x), U(va1.x), U(va0.y), U(va1.y), vb[nb].x, vb[nb].y);
                        mma8(acc[r][nb], U(va0.z), U(va1.z), U(va0.w), U(va1.w), vb[nb].z, vb[nb].w);
                    }
                }
            }
        }
    }

    // epilogue: bias (+resid) (+relu), NHWC float2 stores
#pragma unroll
    for (int r = 0; r < 2; r++) {
        int oy = by + wr0 + r;
        long rowbase = (long)(n * H + oy) * W;
#pragma unroll
        for (int nb = 0; nb < NB; nb++) {
            int co = nb * 8 + 2 * t;
            float bv0 = bias[co], bv1 = bias[co + 1];
            long i0 = (rowbase + bx + g) * COUT + co;
            long i1 = (rowbase + bx + g + 8) * COUT + co;
            float2 v0 = make_float2(acc[r][nb][0] + bv0, acc[r][nb][1] + bv1);
            float2 v1 = make_float2(acc[r][nb][2] + bv0, acc[r][nb][3] + bv1);
            if (RESID) {
                float2 r0 = *(const float2*)(resid + i0);
                float2 r1 = *(const float2*)(resid + i1);
                v0.x += r0.x; v0.y += r0.y; v1.x += r1.x; v1.y += r1.y;
            }
            if (RELU_OUT) {
                v0.x = fmaxf(v0.x, 0.0f); v0.y = fmaxf(v0.y, 0.0f);
                v1.x = fmaxf(v1.x, 0.0f); v1.y = fmaxf(v1.y, 0.0f);
            }
            *(float2*)(out + i0) = v0;
            *(float2*)(out + i1) = v1;
        }
    }
}

// ---------------- maxpool 3x3 s2 p1, NHWC ----------------
__global__ void maxpool_nhwc(const float* __restrict__ in, float* __restrict__ out,
                             int C, int H, int W) {
    int H2 = H >> 1, W2 = W >> 1;
    long total = (long)512 * H2 * W2 * C;
    long i = (long)blockIdx.x * blockDim.x + threadIdx.x;
    if (i >= total) return;
    int c = (int)(i % C); long r = i / C;
    int ox = (int)(r % W2); r /= W2;
    int oy = (int)(r % H2); int n = (int)(r / H2);
    float m = -3.4e38f;
    int y0 = oy * 2 - 1, x0 = ox * 2 - 1;
#pragma unroll
    for (int dy = 0; dy < 3; dy++) {
        int y = y0 + dy;
        if (y < 0 || y >= H) continue;
#pragma unroll
        for (int dx = 0; dx < 3; dx++) {
            int x = x0 + dx;
            if (x < 0 || x >= W) continue;
            m = fmaxf(m, in[((long)(n * H + y) * W + x) * C + c]);
        }
    }
    out[i] = m;
}

// ---------------- CBAM ----------------
__global__ void cbam_ca_nhwc(const float* __restrict__ x, const float* __restrict__ fc1,
                             const float* __restrict__ fc2, float* __restrict__ ca) {
    int n = blockIdx.x, tid = threadIdx.x;
    int g = tid >> 5, c = tid & 31;
    __shared__ float rs[8][32], rm[8][32], s_mean[32], s_max[32], s_h[8];
    float sm = 0.0f, mx = -3.4e38f;
    for (int p = g; p < 256; p += 8) {
        float v = x[((long)n * 256 + p) * 32 + c];
        sm += v; mx = fmaxf(mx, v);
    }
    rs[g][c] = sm; rm[g][c] = mx;
    __syncthreads();
    if (tid < 32) {
        float s = 0.0f, m = -3.4e38f;
        for (int q = 0; q < 8; q++) { s += rs[q][tid]; m = fmaxf(m, rm[q][tid]); }
        s_mean[tid] = s * (1.0f / 256.0f); s_max[tid] = m;
    }
    __syncthreads();
    if (tid < 8) {
        float hm = 0.0f, hx = 0.0f;
        for (int k = 0; k < 32; k++) {
            float wv = fc1[tid * 32 + k];
            hm += s_mean[k] * wv; hx += s_max[k] * wv;
        }
        s_h[tid] = fmaxf(hm, 0.0f) + fmaxf(hx, 0.0f);
    }
    __syncthreads();
    if (tid < 32) {
        float o = 0.0f;
        for (int j = 0; j < 8; j++) o += s_h[j] * fc2[tid * 8 + j];
        ca[n * 32 + tid] = sigf(o);
    }
}

__global__ void cbam_apply_nhwc(float* x, const float* __restrict__ ca, float* __restrict__ sp) {
    int n = blockIdx.x, p = threadIdx.x;
    __shared__ float s_ca[32];
    if (p < 32) s_ca[p] = ca[n * 32 + p];
    __syncthreads();
    float* base = x + ((long)n * 256 + p) * 32;
    float sum = 0.0f, mx = -3.4e38f;
#pragma unroll
    for (int c = 0; c < 32; c++) {
        float v = base[c] * s_ca[c];
        base[c] = v;
        sum += v; mx = fmaxf(mx, v);
    }
    sp[(long)n * 512 + p] = sum * (1.0f / 32.0f);
    sp[(long)n * 512 + 256 + p] = mx;
}

__global__ void cbam_sa_nhwc(float* x, const float* __restrict__ sp, const float* __restrict__ spw) {
    int n = blockIdx.x, p = threadIdx.x;
    int oy = p >> 4, ox = p & 15;
    __shared__ float s_sp[512], s_w[98];
    s_sp[p] = sp[(long)n * 512 + p];
    s_sp[256 + p] = sp[(long)n * 512 + 256 + p];
    if (p < 98) s_w[p] = spw[p];
    __syncthreads();
    float a = 0.0f;
#pragma unroll
    for (int ci = 0; ci < 2; ci++)
        for (int ky = 0; ky < 7; ky++) {
            int y = oy + ky - 3;
            if (y < 0 || y >= 16) continue;
            for (int kx = 0; kx < 7; kx++) {
                int xx = ox + kx - 3;
                if (xx < 0 || xx >= 16) continue;
                a = fmaf(s_sp[ci * 256 + y * 16 + xx], s_w[(ci * 7 + ky) * 7 + kx], a);
            }
        }
    float sa = sigf(a);
    float* base = x + ((long)n * 256 + p) * 32;
#pragma unroll
    for (int c = 0; c < 32; c++) base[c] *= sa;
}

// permute fc_w[n][c*256+p] -> g_fcwT[n][p*32+c] (matches NHWC flatten)
__global__ void fcw_permute(const float* __restrict__ w, float* __restrict__ wt) {
    int i = blockIdx.x * 256 + threadIdx.x;
    if (i >= 256 * 8192) return;
    int n = i >> 13;
    int r = i & 8191;
    int c = r >> 8, p = r & 255;
    wt[(n << 13) + p * 32 + c] = w[i];
}

// ---------------- GEMM: C[M,N] = A[M,K] @ B[N,K]^T + bias, opt relu ------
__global__ void gemm_bt_kernel(const float* __restrict__ A, const float* __restrict__ B,
                               const float* __restrict__ bias, float* __restrict__ C,
                               int M, int N, int K, int relu) {
    __shared__ float sA[32 * 33];
    __shared__ float sB[32 * 33];
    int bm = blockIdx.y * 32, bn = blockIdx.x * 32;
    int tid = threadIdx.x;
    int tr = tid >> 4, tc = tid & 15;
    float acc00 = 0, acc01 = 0, acc10 = 0, acc11 = 0;
    for (int k0 = 0; k0 < K; k0 += 32) {
        for (int i = tid; i < 32 * 32; i += 256) {
            int r = i >> 5, c = i & 31;
            sA[r * 33 + c] = (bm + r < M) ? A[(long)(bm + r) * K + k0 + c] : 0.0f;
            sB[r * 33 + c] = (bn + r < N) ? B[(long)(bn + r) * K + k0 + c] : 0.0f;
        }
        __syncthreads();
#pragma unroll
        for (int k = 0; k < 32; k++) {
            float a0 = sA[(tr * 2) * 33 + k], a1 = sA[(tr * 2 + 1) * 33 + k];
            float b0 = sB[(tc * 2) * 33 + k], b1 = sB[(tc * 2 + 1) * 33 + k];
            acc00 = fmaf(a0, b0, acc00); acc01 = fmaf(a0, b1, acc01);
            acc10 = fmaf(a1, b0, acc10); acc11 = fmaf(a1, b1, acc11);
        }
        __syncthreads();
    }
    float accs[2][2] = {{acc00, acc01}, {acc10, acc11}};
#pragma unroll
    for (int r = 0; r < 2; r++)
#pragma unroll
        for (int c = 0; c < 2; c++) {
            int m = bm + tr * 2 + r, nn = bn + tc * 2 + c;
            if (m < M && nn < N) {
                float v = accs[r][c] + bias[nn];
                if (relu) v = fmaxf(v, 0.0f);
                C[(long)m * N + nn] = v;
            }
        }
}

// ---------------- GRU scan ----------------
__global__ void gru_scan_kernel(const float* __restrict__ gi, const float* __restrict__ done,
                                const float* __restrict__ h0, const float* __restrict__ whh,
                                const float* __restrict__ bhh, float* __restrict__ hidden) {
    extern __shared__ float sm[];
    float* s_whh = sm;
    float* s_gh = sm + 128 * 384;
    float* s_h = s_gh + 384;
    float* s_hm = s_h + 128;
    int b = blockIdx.x, j = threadIdx.x;

    for (int i = j; i < 384 * 128; i += 384) {
        int jj = i >> 7, k = i & 127;
        s_whh[k * 384 + jj] = whh[i];
    }
    if (j < 128) s_h[j] = h0[b * 128 + j];
    __syncthreads();

    float bh = bhh[j];
    for (int t = 0; t < 64; t++) {
        float dt = done[t * 8 + b];
        if (j < 128) s_hm[j] = (1.0f - dt) * s_h[j];
        __syncthreads();
        float acc = bh;
#pragma unroll 8
        for (int k = 0; k < 128; k++) acc = fmaf(s_hm[k], s_whh[k * 384 + j], acc);
        s_gh[j] = acc;
        __syncthreads();
        if (j < 128) {
            const float* gr = gi + (long)(t * 8 + b) * 384;
            float r = sigf(gr[j] + s_gh[j]);
            float z = sigf(gr[128 + j] + s_gh[128 + j]);
            float nn = tanhf(gr[256 + j] + r * s_gh[256 + j]);
            float hn = (1.0f - z) * nn + z * s_hm[j];
            s_h[j] = hn;
            hidden[(long)(t * 8 + b) * 128 + j] = hn;
        }
        __syncthreads();
    }
}

// ---------------- actor/critic heads ----------------
__global__ void heads_kernel(const float* __restrict__ hidden, const float* __restrict__ aw,
                             const float* __restrict__ ab, const float* __restrict__ cw,
                             const float* __restrict__ cb, float* __restrict__ out) {
    int row = blockIdx.x, t = threadIdx.x;
    __shared__ float s_h[128];
    s_h[t] = hidden[(long)row * 128 + t];
    __syncthreads();
    if (t < 4) {
        const float* w = (t < 3) ? (aw + t * 128) : cw;
        float s = (t < 3) ? ab[t] : cb[0];
        for (int k = 0; k < 128; k++) s = fmaf(s_h[k], w[k], s);
        out[row * 4 + t] = s;
    }
}

// ---------------- host-side launch helpers ----------------
template <int CIN, int COUT, bool RELU_IN, bool RESID, bool RELU_OUT, bool NCHW>
static void launch_conv(const float* in, const float* wperm, const float* b,
                        float* out, const float* resid, int H, int W) {
    constexpr int CINP = (CIN <= 8) ? 8 : ((CIN <= 16) ? 16 : 32);
    int smem = 324 * CINP * 4;
    auto kfn = conv_mma_kernel<CIN, COUT, RELU_IN, RESID, RELU_OUT, NCHW>;
    cudaFuncSetAttribute(kfn, cudaFuncAttributeMaxDynamicSharedMemorySize, smem);
    dim3 grid(W / 16, H / 16, 512);
    kfn<<<grid, 256, smem>>>(in, wperm, b, out, resid, H, W);
}

static void launch_wperm(const float* src, float* dst, int CIN, int CINP, int COUT, int nconv) {
    int total = nconv * COUT * CINP * 9;
    wperm_kernel<<<(total + 255) / 256, 256>>>(src, dst, CIN, CINP, COUT, nconv);
}

static void launch_pool(const float* in, float* out, int C, int H, int W) {
    long total = (long)512 * C * (H / 2) * (W / 2);
    maxpool_nhwc<<<(unsigned)((total + 255) / 256), 256>>>(in, out, C, H, W);
}

extern "C" void kernel_launch(void* const* d_in, const int* in_sizes, int n_in,
                              void* d_out, int out_size) {
    (void)in_sizes; (void)n_in; (void)out_size;
    const float* x        = (const float*)d_in[0];
    const float* done     = (const float*)d_in[1];
    const float* grustate = (const float*)d_in[2];
    const float* s0_cw = (const float*)d_in[3];
    const float* s0_cb = (const float*)d_in[4];
    const float* s0_rw = (const float*)d_in[5];
    const float* s0_rb = (const float*)d_in[6];
    const float* s1_cw = (const float*)d_in[7];
    const float* s1_cb = (const float*)d_in[8];
    const float* s1_rw = (const float*)d_in[9];
    const float* s1_rb = (const float*)d_in[10];
    const float* s2_cw = (const float*)d_in[11];
    const float* s2_cb = (const float*)d_in[12];
    const float* s2_rw = (const float*)d_in[13];
    const float* s2_rb = (const float*)d_in[14];
    const float* cbam_fc1 = (const float*)d_in[15];
    const float* cbam_fc2 = (const float*)d_in[16];
    const float* cbam_spw = (const float*)d_in[17];
    const float* fc_w  = (const float*)d_in[18];
    const float* fc_b  = (const float*)d_in[19];
    const float* gwih  = (const float*)d_in[20];
    const float* gwhh  = (const float*)d_in[21];
    const float* gbih  = (const float*)d_in[22];
    const float* gbhh  = (const float*)d_in[23];
    const float* aw    = (const float*)d_in[24];
    const float* ab    = (const float*)d_in[25];
    const float* cw    = (const float*)d_in[26];
    const float* cb    = (const float*)d_in[27];
    float* out = (float*)d_out;

    float *P, *X, *O, *CA, *SP, *FEAT, *GI, *HID, *FCWT, *WP;
    cudaGetSymbolAddress((void**)&P, g_P);
    cudaGetSymbolAddress((void**)&X, g_X);
    cudaGetSymbolAddress((void**)&O, g_O);
    cudaGetSymbolAddress((void**)&CA, g_ca);
    cudaGetSymbolAddress((void**)&SP, g_sp);
    cudaGetSymbolAddress((void**)&FEAT, g_feat);
    cudaGetSymbolAddress((void**)&GI, g_gi);
    cudaGetSymbolAddress((void**)&HID, g_hid);
    cudaGetSymbolAddress((void**)&FCWT, g_fcwT);
    cudaGetSymbolAddress((void**)&WP, g_wperm);

    // weight scratch offsets
    const int OFF_S0C = 0;                        // 1*9*16*8   = 1152
    const int OFF_S0R = 1152;                     // 4*9*16*16  = 9216
    const int OFF_S1C = 10368;                    // 1*9*32*16  = 4608
    const int OFF_S1R = 14976;                    // 4*9*32*32  = 36864
    const int OFF_S2C = 51840;                    // 1*9*32*32  = 9216
    const int OFF_S2R = 61056;                    // 4*9*32*32  = 36864

    // prepasses: conv weight + fc weight permutes
    launch_wperm(s0_cw, WP + OFF_S0C, 6, 8, 16, 1);
    launch_wperm(s0_rw, WP + OFF_S0R, 16, 16, 16, 4);
    launch_wperm(s1_cw, WP + OFF_S1C, 16, 16, 32, 1);
    launch_wperm(s1_rw, WP + OFF_S1R, 32, 32, 32, 4);
    launch_wperm(s2_cw, WP + OFF_S2C, 32, 32, 32, 1);
    launch_wperm(s2_rw, WP + OFF_S2R, 32, 32, 32, 4);
    fcw_permute<<<(256 * 8192 + 255) / 256, 256>>>(fc_w, FCWT);

    // ---- stage 0: 6->16 @128 (NCHW src) -> pool 64 -> 2 resblocks ----
    launch_conv<6, 16, false, false, false, true>(x, WP + OFF_S0C, s0_cb, P, nullptr, 128, 128);
    launch_pool(P, X, 16, 128, 128);
    launch_conv<16, 16, true, false, false, false>(X, WP + OFF_S0R + 0 * 2304, s0_rb + 0,  O, nullptr, 64, 64);
    launch_conv<16, 16, true, true,  false, false>(O, WP + OFF_S0R + 1 * 2304, s0_rb + 16, X, X, 64, 64);
    launch_conv<16, 16, true, false, false, false>(X, WP + OFF_S0R + 2 * 2304, s0_rb + 32, O, nullptr, 64, 64);
    launch_conv<16, 16, true, true,  false, false>(O, WP + OFF_S0R + 3 * 2304, s0_rb + 48, X, X, 64, 64);

    // ---- stage 1: 16->32 @64 -> pool 32 -> 2 resblocks ----
    launch_conv<16, 32, false, false, false, false>(X, WP + OFF_S1C, s1_cb, P, nullptr, 64, 64);
    launch_pool(P, X, 32, 64, 64);
    launch_conv<32, 32, true, false, false, false>(X, WP + OFF_S1R + 0 * 9216, s1_rb + 0,  O, nullptr, 32, 32);
    launch_conv<32, 32, true, true,  false, false>(O, WP + OFF_S1R + 1 * 9216, s1_rb + 32, X, X, 32, 32);
    launch_conv<32, 32, true, false, false, false>(X, WP + OFF_S1R + 2 * 9216, s1_rb + 64, O, nullptr, 32, 32);
    launch_conv<32, 32, true, true,  false, false>(O, WP + OFF_S1R + 3 * 9216, s1_rb + 96, X, X, 32, 32);

    // ---- stage 2: 32->32 @32 -> pool 16 -> 2 resblocks (last fuses final relu) ----
    launch_conv<32, 32, false, false, false, false>(X, WP + OFF_S2C, s2_cb, P, nullptr, 32, 32);
    launch_pool(P, X, 32, 32, 32);
    launch_conv<32, 32, true, false, false, false>(X, WP + OFF_S2R + 0 * 9216, s2_rb + 0,  O, nullptr, 16, 16);
    launch_conv<32, 32, true, true,  false, false>(O, WP + OFF_S2R + 1 * 9216, s2_rb + 32, X, X, 16, 16);
    launch_conv<32, 32, true, false, false, false>(X, WP + OFF_S2R + 2 * 9216, s2_rb + 64, O, nullptr, 16, 16);
    launch_conv<32, 32, true, true,  true,  false>(O, WP + OFF_S2R + 3 * 9216, s2_rb + 96, X, X, 16, 16);

    // ---- CBAM (NHWC) ----
    cbam_ca_nhwc<<<512, 256>>>(X, cbam_fc1, cbam_fc2, CA);
    cbam_apply_nhwc<<<512, 256>>>(X, CA, SP);
    cbam_sa_nhwc<<<512, 256>>>(X, SP, cbam_spw);

    // ---- FC 8192->256 (+relu), NHWC-k permuted weights ----
    gemm_bt_kernel<<<dim3(256 / 32, 512 / 32), 256>>>(X, FCWT, fc_b, FEAT, 512, 256, 8192, 1);

    // ---- GRU: input gates GEMM, then sequential scan ----
    gemm_bt_kernel<<<dim3(384 / 32, 512 / 32), 256>>>(FEAT, gwih, gbih, GI, 512, 384, 256, 0);
    {
        int smem = (128 * 384 + 384 + 128 + 128) * 4;
        cudaFuncSetAttribute(gru_scan_kernel, cudaFuncAttributeMaxDynamicSharedMemorySize, smem);
        gru_scan_kernel<<<8, 384, smem>>>(GI, done, grustate, gwhh, gbhh, HID);
    }

    // ---- actor / critic heads -> (512, 4) ----
    heads_kernel<<<512, 128>>>(HID, aw, ab, cw, cb, out);
}

// round 6
// speedup vs baseline: 1.6694x; 1.0889x over previous
#include <cuda_runtime.h>
#include <math.h>

// ---------------- scratch (device globals; no allocations) ----------------
__device__ float g_P[16777216];    // 64 MiB: pre-pool chunk buffer (L2-resident)
__device__ float g_X[33554432];    // stage state (NHWC)
__device__ float g_O[33554432];    // resblock temp (NHWC)
__device__ float g_ca[512 * 32];
__device__ float g_sp[512 * 2 * 256];
__device__ float g_feat[512 * 256];
__device__ float g_gi[512 * 384];
__device__ float g_hid[512 * 128];
__device__ float g_fcwT[256 * 8192];   // fc_w permuted to NHWC-k order
__device__ float g_wperm[131072];      // all conv weights, tf32 [tap][co][slot(ci)]

__device__ __forceinline__ float sigf(float x) { return 1.0f / (1.0f + expf(-x)); }

__device__ __forceinline__ unsigned tf32u(float x) {
    unsigned r;
    asm("cvt.rna.tf32.f32 %0, %1;" : "=r"(r) : "f"(x));
    return r;
}
__device__ __forceinline__ float tf32f(float x) { return __uint_as_float(tf32u(x)); }

__device__ __forceinline__ void mma8(float* c, unsigned a0, unsigned a1, unsigned a2, unsigned a3,
                                     float b0f, float b1f) {
    unsigned b0 = __float_as_uint(b0f), b1 = __float_as_uint(b1f);
    asm volatile(
        "mma.sync.aligned.m16n8k8.row.col.f32.tf32.tf32.f32 "
        "{%0,%1,%2,%3},{%4,%5,%6,%7},{%8,%9},{%0,%1,%2,%3};"
        : "+f"(c[0]), "+f"(c[1]), "+f"(c[2]), "+f"(c[3])
        : "r"(a0), "r"(a1), "r"(a2), "r"(a3), "r"(b0), "r"(b1));
}
#define U(x) __float_as_uint(x)

// k-slot permutations: contiguous float2/float4 per lane covers k = t, t+4, t+8, t+12
__device__ __forceinline__ int slotp(int k, int CINP) {
    if (CINP == 8)  return 2 * (k & 3) + (k >> 2);
    if (CINP == 16) return 4 * (k & 3) + (k >> 2);
    return 4 * (k & 3) + ((k >> 2) & 3) + ((k >> 4) << 4);
}

// ---------------- fused weight permute prepass (all 6 conv weight sets) ----
__global__ void wperm_all_kernel(const float* __restrict__ s0c, const float* __restrict__ s0r,
                                 const float* __restrict__ s1c, const float* __restrict__ s1r,
                                 const float* __restrict__ s2c, const float* __restrict__ s2r,
                                 float* __restrict__ dst) {
    int i = blockIdx.x * 256 + threadIdx.x;
    if (i >= 97920) return;
    const float* src; int CIN, CINP, COUT, base;
    if (i < 1152)       { src = s0c; CIN = 6;  CINP = 8;  COUT = 16; base = 0; }
    else if (i < 10368) { src = s0r; CIN = 16; CINP = 16; COUT = 16; base = 1152; }
    else if (i < 14976) { src = s1c; CIN = 16; CINP = 16; COUT = 32; base = 10368; }
    else if (i < 51840) { src = s1r; CIN = 32; CINP = 32; COUT = 32; base = 14976; }
    else if (i < 61056) { src = s2c; CIN = 32; CINP = 32; COUT = 32; base = 51840; }
    else                { src = s2r; CIN = 32; CINP = 32; COUT = 32; base = 61056; }
    int li = i - base;
    int tap = li % 9; int r = li / 9;
    int ci = r % CINP; r /= CINP;
    int co = r % COUT; int cv = r / COUT;
    float v = (ci < CIN) ? src[((cv * COUT + co) * CIN + ci) * 9 + tap] : 0.0f;
    dst[base + cv * 9 * COUT * CINP + (tap * COUT + co) * CINP + slotp(ci, CINP)] = tf32f(v);
}

// ---------------- 3x3 conv pad=1, tf32 MMA, weights from global ----------
template <int CIN, int COUT, bool RELU_IN, bool RESID, bool RELU_OUT, bool NCHW>
__global__ __launch_bounds__(256) void conv_mma_kernel(
    const float* __restrict__ in, const float* __restrict__ wperm,
    const float* __restrict__ bias, float* __restrict__ out,
    const float* __restrict__ resid, int H, int W) {
    constexpr int CINP = (CIN <= 8) ? 8 : ((CIN <= 16) ? 16 : 32);
    constexpr int NB = COUT / 8;
    constexpr int A_SZ = 324 * CINP;   // 18*18 halo pixels

    extern __shared__ float s_in[];
    const int tid = threadIdx.x;
    const int n = blockIdx.z;
    const int by = blockIdx.y * 16, bx = blockIdx.x * 16;

    for (int i = tid; i < A_SZ; i += 256) s_in[i] = 0.0f;
    __syncthreads();

    if (NCHW) {
        for (int i = tid; i < 324 * CIN; i += 256) {
            int ci = i / 324, pix = i - ci * 324;
            int iy = pix / 18, ix = pix - iy * 18;
            int gy = by + iy - 1, gx = bx + ix - 1;
            if (gy >= 0 && gy < H && gx >= 0 && gx < W) {
                float v = in[((long)(n * CIN + ci) * H + gy) * W + gx];
                if (RELU_IN) v = fmaxf(v, 0.0f);
                int sl = slotp(ci, CINP);
                if (CINP == 32) sl ^= (pix & 1) << 4;
                s_in[pix * CINP + sl] = tf32f(v);
            }
        }
    } else {
        constexpr int C4 = CIN / 4;
        for (int i = tid; i < 324 * C4; i += 256) {
            int pix = i / C4, c4 = i - pix * C4;
            int iy = pix / 18, ix = pix - iy * 18;
            int gy = by + iy - 1, gx = bx + ix - 1;
            if (gy >= 0 && gy < H && gx >= 0 && gx < W) {
                float4 v = *(const float4*)(in + ((long)(n * H + gy) * W + gx) * CIN + 4 * c4);
                if (RELU_IN) {
                    v.x = fmaxf(v.x, 0.0f); v.y = fmaxf(v.y, 0.0f);
                    v.z = fmaxf(v.z, 0.0f); v.w = fmaxf(v.w, 0.0f);
                }
                int px = (CINP == 32) ? ((pix & 1) << 4) : 0;
                float* dst = s_in + pix * CINP;
                dst[slotp(4 * c4 + 0, CINP) ^ px] = tf32f(v.x);
                dst[slotp(4 * c4 + 1, CINP) ^ px] = tf32f(v.y);
                dst[slotp(4 * c4 + 2, CINP) ^ px] = tf32f(v.z);
                dst[slotp(4 * c4 + 3, CINP) ^ px] = tf32f(v.w);
            }
        }
    }
    __syncthreads();

    const int warp = tid >> 5, lane = tid & 31, g = lane >> 2, t = lane & 3;
    const int wr0 = warp * 2;

    float acc[2][NB][4];
#pragma unroll
    for (int r = 0; r < 2; r++)
#pragma unroll
        for (int nb = 0; nb < NB; nb++)
#pragma unroll
            for (int q = 0; q < 4; q++) acc[r][nb][q] = 0.0f;

#pragma unroll
    for (int tap = 0; tap < 9; tap++) {
        const int dy = tap / 3 - 1, dx = tap % 3 - 1;
        if (CINP == 8) {
            float2 vb[NB];
#pragma unroll
            for (int nb = 0; nb < NB; nb++)
                vb[nb] = *(const float2*)(wperm + (tap * COUT + nb * 8 + g) * 8 + 2 * t);
#pragma unroll
            for (int r = 0; r < 2; r++) {
                int prow = (wr0 + r + dy + 1) * 18 + dx + 1;
                float2 va0 = *(const float2*)(s_in + (prow + g) * 8 + 2 * t);
                float2 va1 = *(const float2*)(s_in + (prow + g + 8) * 8 + 2 * t);
#pragma unroll
                for (int nb = 0; nb < NB; nb++)
                    mma8(acc[r][nb], U(va0.x), U(va1.x), U(va0.y), U(va1.y), vb[nb].x, vb[nb].y);
            }
        } else if (CINP == 16) {
            float4 vb[NB];
#pragma unroll
            for (int nb = 0; nb < NB; nb++)
                vb[nb] = *(const float4*)(wperm + (tap * COUT + nb * 8 + g) * 16 + 4 * t);
#pragma unroll
            for (int r = 0; r < 2; r++) {
                int prow = (wr0 + r + dy + 1) * 18 + dx + 1;
                float4 va0 = *(const float4*)(s_in + (prow + g) * 16 + 4 * t);
                float4 va1 = *(const float4*)(s_in + (prow + g + 8) * 16 + 4 * t);
#pragma unroll
                for (int nb = 0; nb < NB; nb++) {
                    mma8(acc[r][nb], U(va0.x), U(va1.x), U(va0.y), U(va1.y), vb[nb].x, vb[nb].y);
                    mma8(acc[r][nb], U(va0.z), U(va1.z), U(va0.w), U(va1.w), vb[nb].z, vb[nb].w);
                }
            }
        } else {  // CINP == 32: two 16-channel halves, A parity-XOR swizzle
            const int ppar = (dx + 1 + g) & 1;
#pragma unroll
            for (int kb = 0; kb < 2; kb++) {
                float4 vb[NB];
#pragma unroll
                for (int nb = 0; nb < NB; nb++)
                    vb[nb] = *(const float4*)(wperm + (tap * COUT + nb * 8 + g) * 32 + 4 * t + 16 * kb);
                const int koff = 4 * t + (((kb ^ ppar) & 1) << 4);
#pragma unroll
                for (int r = 0; r < 2; r++) {
                    int prow = (wr0 + r + dy + 1) * 18 + dx + 1;
                    float4 va0 = *(const float4*)(s_in + (prow + g) * 32 + koff);
                    float4 va1 = *(const float4*)(s_in + (prow + g + 8) * 32 + koff);
#pragma unroll
                    for (int nb = 0; nb < NB; nb++) {
                        mma8(acc[r][nb], U(va0.x), U(va1.x), U(va0.y), U(va1.y), vb[nb].x, vb[nb].y);
                        mma8(acc[r][nb], U(va0.z), U(va1.z), U(va0.w), U(va1.w), vb[nb].z, vb[nb].w);
                    }
                }
            }
        }
    }

    // epilogue: bias (+resid) (+relu), NHWC float2 stores
#pragma unroll
    for (int r = 0; r < 2; r++) {
        int oy = by + wr0 + r;
        long rowbase = (long)(n * H + oy) * W;
#pragma unroll
        for (int nb = 0; nb < NB; nb++) {
            int co = nb * 8 + 2 * t;
            float bv0 = bias[co], bv1 = bias[co + 1];
            long i0 = (rowbase + bx + g) * COUT + co;
            long i1 = (rowbase + bx + g + 8) * COUT + co;
            float2 v0 = make_float2(acc[r][nb][0] + bv0, acc[r][nb][1] + bv1);
            float2 v1 = make_float2(acc[r][nb][2] + bv0, acc[r][nb][3] + bv1);
            if (RESID) {
                float2 r0 = *(const float2*)(resid + i0);
                float2 r1 = *(const float2*)(resid + i1);
                v0.x += r0.x; v0.y += r0.y; v1.x += r1.x; v1.y += r1.y;
            }
            if (RELU_OUT) {
                v0.x = fmaxf(v0.x, 0.0f); v0.y = fmaxf(v0.y, 0.0f);
                v1.x = fmaxf(v1.x, 0.0f); v1.y = fmaxf(v1.y, 0.0f);
            }
            *(float2*)(out + i0) = v0;
            *(float2*)(out + i1) = v1;
        }
    }
}

// ---------------- maxpool 3x3 s2 p1, NHWC, batch-chunk sized ----------------
__global__ void maxpool_nhwc(const float* __restrict__ in, float* __restrict__ out,
                             int NTOT, int C, int H, int W) {
    int H2 = H >> 1, W2 = W >> 1;
    long total = (long)NTOT * H2 * W2 * C;
    long i = (long)blockIdx.x * blockDim.x + threadIdx.x;
    if (i >= total) return;
    int c = (int)(i % C); long r = i / C;
    int ox = (int)(r % W2); r /= W2;
    int oy = (int)(r % H2); int n = (int)(r / H2);
    float m = -3.4e38f;
    int y0 = oy * 2 - 1, x0 = ox * 2 - 1;
#pragma unroll
    for (int dy = 0; dy < 3; dy++) {
        int y = y0 + dy;
        if (y < 0 || y >= H) continue;
#pragma unroll
        for (int dx = 0; dx < 3; dx++) {
            int x = x0 + dx;
            if (x < 0 || x >= W) continue;
            m = fmaxf(m, in[((long)(n * H + y) * W + x) * C + c]);
        }
    }
    out[i] = m;
}

// ---------------- CBAM ----------------
__global__ void cbam_ca_nhwc(const float* __restrict__ x, const float* __restrict__ fc1,
                             const float* __restrict__ fc2, float* __restrict__ ca) {
    int n = blockIdx.x, tid = threadIdx.x;
    int g = tid >> 5, c = tid & 31;
    __shared__ float rs[8][32], rm[8][32], s_mean[32], s_max[32], s_h[8];
    float sm = 0.0f, mx = -3.4e38f;
    for (int p = g; p < 256; p += 8) {
        float v = x[((long)n * 256 + p) * 32 + c];
        sm += v; mx = fmaxf(mx, v);
    }
    rs[g][c] = sm; rm[g][c] = mx;
    __syncthreads();
    if (tid < 32) {
        float s = 0.0f, m = -3.4e38f;
        for (int q = 0; q < 8; q++) { s += rs[q][tid]; m = fmaxf(m, rm[q][tid]); }
        s_mean[tid] = s * (1.0f / 256.0f); s_max[tid] = m;
    }
    __syncthreads();
    if (tid < 8) {
        float hm = 0.0f, hx = 0.0f;
        for (int k = 0; k < 32; k++) {
            float wv = fc1[tid * 32 + k];
            hm += s_mean[k] * wv; hx += s_max[k] * wv;
        }
        s_h[tid] = fmaxf(hm, 0.0f) + fmaxf(hx, 0.0f);
    }
    __syncthreads();
    if (tid < 32) {
        float o = 0.0f;
        for (int j = 0; j < 8; j++) o += s_h[j] * fc2[tid * 8 + j];
        ca[n * 32 + tid] = sigf(o);
    }
}

__global__ void cbam_apply_nhwc(float* x, const float* __restrict__ ca, float* __restrict__ sp) {
    int n = blockIdx.x, p = threadIdx.x;
    __shared__ float s_ca[32];
    if (p < 32) s_ca[p] = ca[n * 32 + p];
    __syncthreads();
    float* base = x + ((long)n * 256 + p) * 32;
    float sum = 0.0f, mx = -3.4e38f;
#pragma unroll
    for (int c = 0; c < 32; c++) {
        float v = base[c] * s_ca[c];
        base[c] = v;
        sum += v; mx = fmaxf(mx, v);
    }
    sp[(long)n * 512 + p] = sum * (1.0f / 32.0f);
    sp[(long)n * 512 + 256 + p] = mx;
}

__global__ void cbam_sa_nhwc(float* x, const float* __restrict__ sp, const float* __restrict__ spw) {
    int n = blockIdx.x, p = threadIdx.x;
    int oy = p >> 4, ox = p & 15;
    __shared__ float s_sp[512], s_w[98];
    s_sp[p] = sp[(long)n * 512 + p];
    s_sp[256 + p] = sp[(long)n * 512 + 256 + p];
    if (p < 98) s_w[p] = spw[p];
    __syncthreads();
    float a = 0.0f;
#pragma unroll
    for (int ci = 0; ci < 2; ci++)
        for (int ky = 0; ky < 7; ky++) {
            int y = oy + ky - 3;
            if (y < 0 || y >= 16) continue;
            for (int kx = 0; kx < 7; kx++) {
                int xx = ox + kx - 3;
                if (xx < 0 || xx >= 16) continue;
                a = fmaf(s_sp[ci * 256 + y * 16 + xx], s_w[(ci * 7 + ky) * 7 + kx], a);
            }
        }
    float sa = sigf(a);
    float* base = x + ((long)n * 256 + p) * 32;
#pragma unroll
    for (int c = 0; c < 32; c++) base[c] *= sa;
}

// permute fc_w[n][c*256+p] -> g_fcwT[n][p*32+c] (matches NHWC flatten)
__global__ void fcw_permute(const float* __restrict__ w, float* __restrict__ wt) {
    int i = blockIdx.x * 256 + threadIdx.x;
    if (i >= 256 * 8192) return;
    int n = i >> 13;
    int r = i & 8191;
    int c = r >> 8, p = r & 255;
    wt[(n << 13) + p * 32 + c] = w[i];
}

// ---------------- tf32 MMA GEMM: C[M,N] = A[M,K]@B[N,K]^T + bias ----------
// Block 64x64 tile, 8 warps (4 M x 2 N); warp = M16 x N32. K chunked by 32.
template <int RELU>
__global__ __launch_bounds__(256) void gemm_mma_kernel(
    const float* __restrict__ A, const float* __restrict__ B,
    const float* __restrict__ bias, float* __restrict__ C,
    int M, int N, int K) {
    __shared__ float sA[64 * 36], sB[64 * 36];
    const int tid = threadIdx.x;
    const int bm = blockIdx.y * 64, bn = blockIdx.x * 64;
    const int warp = tid >> 5, lane = tid & 31, g = lane >> 2, t = lane & 3;
    const int wm = warp >> 1, wn = warp & 1;
    const int lr = tid >> 2, lc = (tid & 3) * 8;

    float acc[4][4];
#pragma unroll
    for (int i = 0; i < 4; i++)
#pragma unroll
        for (int q = 0; q < 4; q++) acc[i][q] = 0.0f;

    for (int k0 = 0; k0 < K; k0 += 32) {
        float4 va0 = *(const float4*)(A + (long)(bm + lr) * K + k0 + lc);
        float4 va1 = *(const float4*)(A + (long)(bm + lr) * K + k0 + lc + 4);
        float4 vb0 = *(const float4*)(B + (long)(bn + lr) * K + k0 + lc);
        float4 vb1 = *(const float4*)(B + (long)(bn + lr) * K + k0 + lc + 4);
        float* pa = sA + lr * 36 + lc;
        float* pb = sB + lr * 36 + lc;
        pa[0] = tf32f(va0.x); pa[1] = tf32f(va0.y); pa[2] = tf32f(va0.z); pa[3] = tf32f(va0.w);
        pa[4] = tf32f(va1.x); pa[5] = tf32f(va1.y); pa[6] = tf32f(va1.z); pa[7] = tf32f(va1.w);
        pb[0] = tf32f(vb0.x); pb[1] = tf32f(vb0.y); pb[2] = tf32f(vb0.z); pb[3] = tf32f(vb0.w);
        pb[4] = tf32f(vb1.x); pb[5] = tf32f(vb1.y); pb[6] = tf32f(vb1.z); pb[7] = tf32f(vb1.w);
        __syncthreads();
#pragma unroll
        for (int ks = 0; ks < 4; ks++) {
            const int k = ks * 8;
            const int r0 = wm * 16 + g;
            unsigned a0 = U(sA[r0 * 36 + k + t]),       a1 = U(sA[(r0 + 8) * 36 + k + t]);
            unsigned a2 = U(sA[r0 * 36 + k + t + 4]),   a3 = U(sA[(r0 + 8) * 36 + k + t + 4]);
#pragma unroll
            for (int nt = 0; nt < 4; nt++) {
                int nr = wn * 32 + nt * 8 + g;
                mma8(acc[nt], a0, a1, a2, a3, sB[nr * 36 + k + t], sB[nr * 36 + k + t + 4]);
            }
        }
        __syncthreads();
    }
#pragma unroll
    for (int nt = 0; nt < 4; nt++) {
        int n0 = bn + wn * 32 + nt * 8 + 2 * t;
        int m0 = bm + wm * 16 + g;
        float b0 = bias[n0], b1 = bias[n0 + 1];
        float v00 = acc[nt][0] + b0, v01 = acc[nt][1] + b1;
        float v10 = acc[nt][2] + b0, v11 = acc[nt][3] + b1;
        if (RELU) {
            v00 = fmaxf(v00, 0.0f); v01 = fmaxf(v01, 0.0f);
            v10 = fmaxf(v10, 0.0f); v11 = fmaxf(v11, 0.0f);
        }
        C[(long)m0 * N + n0] = v00;       C[(long)m0 * N + n0 + 1] = v01;
        C[(long)(m0 + 8) * N + n0] = v10; C[(long)(m0 + 8) * N + n0 + 1] = v11;
    }
}

// ---------------- GRU scan ----------------
__global__ void gru_scan_kernel(const float* __restrict__ gi, const float* __restrict__ done,
                                const float* __restrict__ h0, const float* __restrict__ whh,
                                const float* __restrict__ bhh, float* __restrict__ hidden) {
    extern __shared__ float sm[];
    float* s_whh = sm;
    float* s_gh = sm + 128 * 384;
    float* s_h = s_gh + 384;
    float* s_hm = s_h + 128;
    int b = blockIdx.x, j = threadIdx.x;

    for (int i = j; i < 384 * 128; i += 384) {
        int jj = i >> 7, k = i & 127;
        s_whh[k * 384 + jj] = whh[i];
    }
    if (j < 128) s_h[j] = h0[b * 128 + j];
    __syncthreads();

    float bh = bhh[j];
    for (int t = 0; t < 64; t++) {
        float dt = done[t * 8 + b];
        if (j < 128) s_hm[j] = (1.0f - dt) * s_h[j];
        __syncthreads();
        float acc = bh;
#pragma unroll 8
        for (int k = 0; k < 128; k++) acc = fmaf(s_hm[k], s_whh[k * 384 + j], acc);
        s_gh[j] = acc;
        __syncthreads();
        if (j < 128) {
            const float* gr = gi + (long)(t * 8 + b) * 384;
            float r = sigf(gr[j] + s_gh[j]);
            float z = sigf(gr[128 + j] + s_gh[128 + j]);
            float nn = tanhf(gr[256 + j] + r * s_gh[256 + j]);
            float hn = (1.0f - z) * nn + z * s_hm[j];
            s_h[j] = hn;
            hidden[(long)(t * 8 + b) * 128 + j] = hn;
        }
        __syncthreads();
    }
}

// ---------------- actor/critic heads ----------------
__global__ void heads_kernel(const float* __restrict__ hidden, const float* __restrict__ aw,
                             const float* __restrict__ ab, const float* __restrict__ cw,
                             const float* __restrict__ cb, float* __restrict__ out) {
    int row = blockIdx.x, t = threadIdx.x;
    __shared__ float s_h[128];
    s_h[t] = hidden[(long)row * 128 + t];
    __syncthreads();
    if (t < 4) {
        const float* w = (t < 3) ? (aw + t * 128) : cw;
        float s = (t < 3) ? ab[t] : cb[0];
        for (int k = 0; k < 128; k++) s = fmaf(s_h[k], w[k], s);
        out[row * 4 + t] = s;
    }
}

// ---------------- host-side launch helpers ----------------
template <int CIN, int COUT, bool RELU_IN, bool RESID, bool RELU_OUT, bool NCHW>
static void launch_conv(const float* in, const float* wperm, const float* b,
                        float* out, const float* resid, int H, int W, int NB) {
    constexpr int CINP = (CIN <= 8) ? 8 : ((CIN <= 16) ? 16 : 32);
    int smem = 324 * CINP * 4;
    auto kfn = conv_mma_kernel<CIN, COUT, RELU_IN, RESID, RELU_OUT, NCHW>;
    cudaFuncSetAttribute(kfn, cudaFuncAttributeMaxDynamicSharedMemorySize, smem);
    dim3 grid(W / 16, H / 16, NB);
    kfn<<<grid, 256, smem>>>(in, wperm, b, out, resid, H, W);
}

static void launch_pool(const float* in, float* out, int NTOT, int C, int H, int W) {
    long total = (long)NTOT * C * (H / 2) * (W / 2);
    maxpool_nhwc<<<(unsigned)((total + 255) / 256), 256>>>(in, out, NTOT, C, H, W);
}

extern "C" void kernel_launch(void* const* d_in, const int* in_sizes, int n_in,
                              void* d_out, int out_size) {
    (void)in_sizes; (void)n_in; (void)out_size;
    const float* x        = (const float*)d_in[0];
    const float* done     = (const float*)d_in[1];
    const float* grustate = (const float*)d_in[2];
    const float* s0_cw = (const float*)d_in[3];
    const float* s0_cb = (const float*)d_in[4];
    const float* s0_rw = (const float*)d_in[5];
    const float* s0_rb = (const float*)d_in[6];
    const float* s1_cw = (const float*)d_in[7];
    const float* s1_cb = (const float*)d_in[8];
    const float* s1_rw = (const float*)d_in[9];
    const float* s1_rb = (const float*)d_in[10];
    const float* s2_cw = (const float*)d_in[11];
    const float* s2_cb = (const float*)d_in[12];
    const float* s2_rw = (const float*)d_in[13];
    const float* s2_rb = (const float*)d_in[14];
    const float* cbam_fc1 = (const float*)d_in[15];
    const float* cbam_fc2 = (const float*)d_in[16];
    const float* cbam_spw = (const float*)d_in[17];
    const float* fc_w  = (const float*)d_in[18];
    const float* fc_b  = (const float*)d_in[19];
    const float* gwih  = (const float*)d_in[20];
    const float* gwhh  = (const float*)d_in[21];
    const float* gbih  = (const float*)d_in[22];
    const float* gbhh  = (const float*)d_in[23];
    const float* aw    = (const float*)d_in[24];
    const float* ab    = (const float*)d_in[25];
    const float* cw    = (const float*)d_in[26];
    const float* cb    = (const float*)d_in[27];
    float* out = (float*)d_out;

    float *P, *X, *O, *CA, *SP, *FEAT, *GI, *HID, *FCWT, *WP;
    cudaGetSymbolAddress((void**)&P, g_P);
    cudaGetSymbolAddress((void**)&X, g_X);
    cudaGetSymbolAddress((void**)&O, g_O);
    cudaGetSymbolAddress((void**)&CA, g_ca);
    cudaGetSymbolAddress((void**)&SP, g_sp);
    cudaGetSymbolAddress((void**)&FEAT, g_feat);
    cudaGetSymbolAddress((void**)&GI, g_gi);
    cudaGetSymbolAddress((void**)&HID, g_hid);
    cudaGetSymbolAddress((void**)&FCWT, g_fcwT);
    cudaGetSymbolAddress((void**)&WP, g_wperm);

    // weight scratch offsets
    const int OFF_S0C = 0;
    const int OFF_S0R = 1152;
    const int OFF_S1C = 10368;
    const int OFF_S1R = 14976;
    const int OFF_S2C = 51840;
    const int OFF_S2R = 61056;

    // prepasses
    wperm_all_kernel<<<(97920 + 255) / 256, 256>>>(s0_cw, s0_rw, s1_cw, s1_rw, s2_cw, s2_rw, WP);
    fcw_permute<<<(256 * 8192 + 255) / 256, 256>>>(fc_w, FCWT);

    // ---- stage 0: 6->16 @128 (NCHW src) -> pool 64, L2-chunked ----
    for (int c = 0; c < 512; c += 64) {
        launch_conv<6, 16, false, false, false, true>(
            x + (long)c * 6 * 128 * 128, WP + OFF_S0C, s0_cb, P, nullptr, 128, 128, 64);
        launch_pool(P, X + (long)c * 16 * 64 * 64, 64, 16, 128, 128);
    }
    launch_conv<16, 16, true, false, false, false>(X, WP + OFF_S0R + 0 * 2304, s0_rb + 0,  O, nullptr, 64, 64, 512);
    launch_conv<16, 16, true, true,  false, false>(O, WP + OFF_S0R + 1 * 2304, s0_rb + 16, X, X, 64, 64, 512);
    launch_conv<16, 16, true, false, false, false>(X, WP + OFF_S0R + 2 * 2304, s0_rb + 32, O, nullptr, 64, 64, 512);
    launch_conv<16, 16, true, true,  false, false>(O, WP + OFF_S0R + 3 * 2304, s0_rb + 48, X, X, 64, 64, 512);

    // ---- stage 1: 16->32 @64 -> pool 32, L2-chunked ----
    for (int c = 0; c < 512; c += 128) {
        launch_conv<16, 32, false, false, false, false>(
            X + (long)c * 64 * 64 * 16, WP + OFF_S1C, s1_cb, P, nullptr, 64, 64, 128);
        launch_pool(P, X + (long)c * 32 * 32 * 32, 128, 32, 64, 64);
    }
    launch_conv<32, 32, true, false, false, false>(X, WP + OFF_S1R + 0 * 9216, s1_rb + 0,  O, nullptr, 32, 32, 512);
    launch_conv<32, 32, true, true,  false, false>(O, WP + OFF_S1R + 1 * 9216, s1_rb + 32, X, X, 32, 32, 512);
    launch_conv<32, 32, true, false, false, false>(X, WP + OFF_S1R + 2 * 9216, s1_rb + 64, O, nullptr, 32, 32, 512);
    launch_conv<32, 32, true, true,  false, false>(O, WP + OFF_S1R + 3 * 9216, s1_rb + 96, X, X, 32, 32, 512);

    // ---- stage 2: 32->32 @32 -> pool 16, L2-chunked; last res fuses final relu ----
    for (int c = 0; c < 512; c += 256) {
        launch_conv<32, 32, false, false, false, false>(
            X + (long)c * 32 * 32 * 32, WP + OFF_S2C, s2_cb, P, nullptr, 32, 32, 256);
        launch_pool(P, X + (long)c * 16 * 16 * 32, 256, 32, 32, 32);
    }
    launch_conv<32, 32, true, false, false, false>(X, WP + OFF_S2R + 0 * 9216, s2_rb + 0,  O, nullptr, 16, 16, 512);
    launch_conv<32, 32, true, true,  false, false>(O, WP + OFF_S2R + 1 * 9216, s2_rb + 32, X, X, 16, 16, 512);
    launch_conv<32, 32, true, false, false, false>(X, WP + OFF_S2R + 2 * 9216, s2_rb + 64, O, nullptr, 16, 16, 512);
    launch_conv<32, 32, true, true,  true,  false>(O, WP + OFF_S2R + 3 * 9216, s2_rb + 96, X, X, 16, 16, 512);

    // ---- CBAM (NHWC) ----
    cbam_ca_nhwc<<<512, 256>>>(X, cbam_fc1, cbam_fc2, CA);
    cbam_apply_nhwc<<<512, 256>>>(X, CA, SP);
    cbam_sa_nhwc<<<512, 256>>>(X, SP, cbam_spw);

    // ---- FC 8192->256 (+relu) and GRU input-gate GEMM, tf32 MMA ----
    gemm_mma_kernel<1><<<dim3(256 / 64, 512 / 64), 256>>>(X, FCWT, fc_b, FEAT, 512, 256, 8192);
    gemm_mma_kernel<0><<<dim3(384 / 64, 512 / 64), 256>>>(FEAT, gwih, gbih, GI, 512, 384, 256);

    // ---- GRU sequential scan ----
    {
        int smem = (128 * 384 + 384 + 128 + 128) * 4;
        cudaFuncSetAttribute(gru_scan_kernel, cudaFuncAttributeMaxDynamicSharedMemorySize, smem);
        gru_scan_kernel<<<8, 384, smem>>>(GI, done, grustate, gwhh, gbhh, HID);
    }

    // ---- actor / critic heads -> (512, 4) ----
    heads_kernel<<<512, 128>>>(HID, aw, ab, cw, cb, out);
}

// round 7
// speedup vs baseline: 1.8374x; 1.1006x over previous
#include <cuda_runtime.h>
#include <math.h>

// ---------------- scratch (device globals; no allocations) ----------------
__device__ float g_X[33554432];    // stage state (NHWC)
__device__ float g_O[33554432];    // stage temp (NHWC)
__device__ float g_ca[512 * 32];
__device__ float g_sp[512 * 2 * 256];
__device__ float g_feat[512 * 256];
__device__ float g_gi[512 * 384];
__device__ float g_hid[512 * 128];
__device__ float g_fcwT[256 * 8192];   // fc_w permuted to NHWC-k order
__device__ float g_wperm[131072];      // all conv weights, tf32 [tap][co][slot(ci)]

__device__ __forceinline__ float sigf(float x) { return 1.0f / (1.0f + expf(-x)); }

__device__ __forceinline__ unsigned tf32u(float x) {
    unsigned r;
    asm("cvt.rna.tf32.f32 %0, %1;" : "=r"(r) : "f"(x));
    return r;
}
__device__ __forceinline__ float tf32f(float x) { return __uint_as_float(tf32u(x)); }

__device__ __forceinline__ void mma8(float* c, unsigned a0, unsigned a1, unsigned a2, unsigned a3,
                                     float b0f, float b1f) {
    unsigned b0 = __float_as_uint(b0f), b1 = __float_as_uint(b1f);
    asm volatile(
        "mma.sync.aligned.m16n8k8.row.col.f32.tf32.tf32.f32 "
        "{%0,%1,%2,%3},{%4,%5,%6,%7},{%8,%9},{%0,%1,%2,%3};"
        : "+f"(c[0]), "+f"(c[1]), "+f"(c[2]), "+f"(c[3])
        : "r"(a0), "r"(a1), "r"(a2), "r"(a3), "r"(b0), "r"(b1));
}
#define U(x) __float_as_uint(x)

__device__ __forceinline__ int slotp(int k, int CINP) {
    if (CINP == 8)  return 2 * (k & 3) + (k >> 2);
    if (CINP == 16) return 4 * (k & 3) + (k >> 2);
    return 4 * (k & 3) + ((k >> 2) & 3) + ((k >> 4) << 4);
}

// ---------------- fused weight permute prepass (all 6 conv weight sets) ----
__global__ void wperm_all_kernel(const float* __restrict__ s0c, const float* __restrict__ s0r,
                                 const float* __restrict__ s1c, const float* __restrict__ s1r,
                                 const float* __restrict__ s2c, const float* __restrict__ s2r,
                                 float* __restrict__ dst) {
    int i = blockIdx.x * 256 + threadIdx.x;
    if (i >= 97920) return;
    const float* src; int CIN, CINP, COUT, base;
    if (i < 1152)       { src = s0c; CIN = 6;  CINP = 8;  COUT = 16; base = 0; }
    else if (i < 10368) { src = s0r; CIN = 16; CINP = 16; COUT = 16; base = 1152; }
    else if (i < 14976) { src = s1c; CIN = 16; CINP = 16; COUT = 32; base = 10368; }
    else if (i < 51840) { src = s1r; CIN = 32; CINP = 32; COUT = 32; base = 14976; }
    else if (i < 61056) { src = s2c; CIN = 32; CINP = 32; COUT = 32; base = 51840; }
    else                { src = s2r; CIN = 32; CINP = 32; COUT = 32; base = 61056; }
    int li = i - base;
    int tap = li % 9; int r = li / 9;
    int ci = r % CINP; r /= CINP;
    int co = r % COUT; int cv = r / COUT;
    float v = (ci < CIN) ? src[((cv * COUT + co) * CIN + ci) * 9 + tap] : 0.0f;
    dst[base + cv * 9 * COUT * CINP + (tap * COUT + co) * CINP + slotp(ci, CINP)] = tf32f(v);
}

// ---------------- fused conv kernel -----------------------------------------
// MODE 0: conv (18x18 region) -> maxpool 3x3 s2 -> out 8x8xCOUT per tile.
// MODE 1: conv1 (18x18) -> relu -> conv2 (16x16) + resid (+relu) -> out.
// Input: 20x20 halo in smem, slot-permuted tf32. Weights from global (wperm).
template <int CIN, int COUT, bool RELU_IN, int MODE, bool RELU_OUT, bool NCHW>
__global__ __launch_bounds__(256) void conv_fused_kernel(
    const float* __restrict__ in, const float* __restrict__ w1,
    const float* __restrict__ b1v, const float* __restrict__ w2,
    const float* __restrict__ b2v, float* __restrict__ out,
    const float* __restrict__ resid, int H, int W) {
    constexpr int CINP = (CIN <= 8) ? 8 : ((CIN <= 16) ? 16 : 32);
    constexpr int COUTP = (COUT <= 8) ? 8 : ((COUT <= 16) ? 16 : 32);
    constexpr int NB = COUT / 8;
    constexpr int IN_SZ = 400 * CINP;
    constexpr int MSTR = (MODE == 0) ? COUT : COUTP;
    constexpr int MID_SZ = 324 * MSTR;

    extern __shared__ float sm[];
    float* s_in = sm;
    float* s_mid = sm + IN_SZ;

    const int tid = threadIdx.x;
    const int n = blockIdx.z;
    const int by = blockIdx.y * 16, bx = blockIdx.x * 16;

    for (int i = tid; i < IN_SZ + MID_SZ; i += 256) sm[i] = 0.0f;
    __syncthreads();

    // ---- stage 20x20 input halo ----
    if (NCHW) {
        for (int i = tid; i < 400 * CIN; i += 256) {
            int ci = i / 400, pix = i - ci * 400;
            int iy = pix / 20, ix = pix - iy * 20;
            int gy = by + iy - 2, gx = bx + ix - 2;
            if (gy >= 0 && gy < H && gx >= 0 && gx < W) {
                float v = in[((long)(n * CIN + ci) * H + gy) * W + gx];
                if (RELU_IN) v = fmaxf(v, 0.0f);
                int sl = slotp(ci, CINP);
                if (CINP == 32) sl ^= (pix & 1) << 4;
                s_in[pix * CINP + sl] = tf32f(v);
            }
        }
    } else {
        constexpr int C4 = CIN / 4;
        for (int i = tid; i < 400 * C4; i += 256) {
            int pix = i / C4, c4 = i - pix * C4;
            int iy = pix / 20, ix = pix - iy * 20;
            int gy = by + iy - 2, gx = bx + ix - 2;
            if (gy >= 0 && gy < H && gx >= 0 && gx < W) {
                float4 v = *(const float4*)(in + ((long)(n * H + gy) * W + gx) * CIN + 4 * c4);
                if (RELU_IN) {
                    v.x = fmaxf(v.x, 0.0f); v.y = fmaxf(v.y, 0.0f);
                    v.z = fmaxf(v.z, 0.0f); v.w = fmaxf(v.w, 0.0f);
                }
                int px = (CINP == 32) ? ((pix & 1) << 4) : 0;
                float* dst = s_in + pix * CINP;
                dst[slotp(4 * c4 + 0, CINP) ^ px] = tf32f(v.x);
                dst[slotp(4 * c4 + 1, CINP) ^ px] = tf32f(v.y);
                dst[slotp(4 * c4 + 2, CINP) ^ px] = tf32f(v.z);
                dst[slotp(4 * c4 + 3, CINP) ^ px] = tf32f(v.w);
            }
        }
    }
    __syncthreads();

    const int warp = tid >> 5, lane = tid & 31, g = lane >> 2, t = lane & 3;

    // ---- conv1 over the 18x18 intermediate region: 3 M16 tiles per warp ----
    float acc1[3][NB][4];
#pragma unroll
    for (int s = 0; s < 3; s++)
#pragma unroll
        for (int nb = 0; nb < NB; nb++)
#pragma unroll
            for (int q = 0; q < 4; q++) acc1[s][nb][q] = 0.0f;

    int base0[3], base1[3];
#pragma unroll
    for (int s = 0; s < 3; s++) {
        int tt = warp + 8 * s;
        int p0 = tt * 16 + g, p1 = p0 + 8;
        int q0 = p0 > 323 ? 323 : p0, q1 = p1 > 323 ? 323 : p1;
        base0[s] = (q0 / 18 + 1) * 20 + (q0 % 18 + 1);
        base1[s] = (q1 / 18 + 1) * 20 + (q1 % 18 + 1);
    }

#pragma unroll
    for (int tap = 0; tap < 9; tap++) {
        const int dy = tap / 3 - 1, dx = tap % 3 - 1;
        const int off = dy * 20 + dx;
        if (CINP == 8) {
            float2 vb[NB];
#pragma unroll
            for (int nb = 0; nb < NB; nb++)
                vb[nb] = *(const float2*)(w1 + (tap * COUT + nb * 8 + g) * 8 + 2 * t);
#pragma unroll
            for (int s = 0; s < 3; s++) {
                float2 va0 = *(const float2*)(s_in + (base0[s] + off) * 8 + 2 * t);
                float2 va1 = *(const float2*)(s_in + (base1[s] + off) * 8 + 2 * t);
#pragma unroll
                for (int nb = 0; nb < NB; nb++)
                    mma8(acc1[s][nb], U(va0.x), U(va1.x), U(va0.y), U(va1.y), vb[nb].x, vb[nb].y);
            }
        } else if (CINP == 16) {
            float4 vb[NB];
#pragma unroll
            for (int nb = 0; nb < NB; nb++)
                vb[nb] = *(const float4*)(w1 + (tap * COUT + nb * 8 + g) * 16 + 4 * t);
#pragma unroll
            for (int s = 0; s < 3; s++) {
                float4 va0 = *(const float4*)(s_in + (base0[s] + off) * 16 + 4 * t);
                float4 va1 = *(const float4*)(s_in + (base1[s] + off) * 16 + 4 * t);
#pragma unroll
                for (int nb = 0; nb < NB; nb++) {
                    mma8(acc1[s][nb], U(va0.x), U(va1.x), U(va0.y), U(va1.y), vb[nb].x, vb[nb].y);
                    mma8(acc1[s][nb], U(va0.z), U(va1.z), U(va0.w), U(va1.w), vb[nb].z, vb[nb].w);
                }
            }
        } else {
#pragma unroll
            for (int kb = 0; kb < 2; kb++) {
                float4 vb[NB];
#pragma unroll
                for (int nb = 0; nb < NB; nb++)
                    vb[nb] = *(const float4*)(w1 + (tap * COUT + nb * 8 + g) * 32 + 4 * t + 16 * kb);
#pragma unroll
                for (int s = 0; s < 3; s++) {
                    int hp0 = base0[s] + off, hp1 = base1[s] + off;
                    int k0 = 4 * t + (((kb ^ hp0) & 1) << 4);
                    int k1 = 4 * t + (((kb ^ hp1) & 1) << 4);
                    float4 va0 = *(const float4*)(s_in + hp0 * 32 + k0);
                    float4 va1 = *(const float4*)(s_in + hp1 * 32 + k1);
#pragma unroll
                    for (int nb = 0; nb < NB; nb++) {
                        mma8(acc1[s][nb], U(va0.x), U(va1.x), U(va0.y), U(va1.y), vb[nb].x, vb[nb].y);
                        mma8(acc1[s][nb], U(va0.z), U(va1.z), U(va0.w), U(va1.w), vb[nb].z, vb[nb].w);
                    }
                }
            }
        }
    }

    // ---- store conv1 results to s_mid ----
#pragma unroll
    for (int s = 0; s < 3; s++) {
        int tt = warp + 8 * s;
        int pbase = tt * 16 + g;
#pragma unroll
        for (int half = 0; half < 2; half++) {
            int p = pbase + 8 * half;
            if (p < 324) {
                int r = p / 18, c = p - r * 18;
                int gy = by - 1 + r, gx = bx - 1 + c;
                if (gy >= 0 && gy < H && gx >= 0 && gx < W) {
#pragma unroll
                    for (int nb = 0; nb < NB; nb++) {
                        int co = nb * 8 + 2 * t;
                        float v0 = acc1[s][nb][2 * half + 0] + b1v[co];
                        float v1 = acc1[s][nb][2 * half + 1] + b1v[co + 1];
                        if (MODE == 0) {
                            s_mid[p * COUT + co] = v0;
                            s_mid[p * COUT + co + 1] = v1;
                        } else {
                            int px = (COUTP == 32) ? ((p & 1) << 4) : 0;
                            s_mid[p * COUTP + (slotp(co, COUTP) ^ px)] = tf32f(fmaxf(v0, 0.0f));
                            s_mid[p * COUTP + (slotp(co + 1, COUTP) ^ px)] = tf32f(fmaxf(v1, 0.0f));
                        }
                    }
                }
            }
        }
    }
    __syncthreads();

    if (MODE == 0) {
        // ---- maxpool 3x3 s2 over s_mid -> 8x8 x COUT ----
        int H2 = H >> 1, W2 = W >> 1;
        for (int o = tid; o < 64 * COUT; o += 256) {
            int co = o % COUT; int pp = o / COUT;
            int ly = pp >> 3, lx = pp & 7;
            float m = -3.4e38f;
#pragma unroll
            for (int dy = 0; dy < 3; dy++) {
                int r = 2 * ly + dy;
                int gy = by - 1 + r;
                if (gy < 0 || gy >= H) continue;
#pragma unroll
                for (int dxx = 0; dxx < 3; dxx++) {
                    int c = 2 * lx + dxx;
                    int gx = bx - 1 + c;
                    if (gx < 0 || gx >= W) continue;
                    m = fmaxf(m, s_mid[(r * 18 + c) * COUT + co]);
                }
            }
            out[(((long)n * H2 + (by / 2 + ly)) * W2 + (bx / 2 + lx)) * COUT + co] = m;
        }
    } else {
        // ---- conv2 16x16 from s_mid (18x18, stride COUTP) ----
        const int wr0 = warp * 2;
        float acc[2][NB][4];
#pragma unroll
        for (int r = 0; r < 2; r++)
#pragma unroll
            for (int nb = 0; nb < NB; nb++)
#pragma unroll
                for (int q = 0; q < 4; q++) acc[r][nb][q] = 0.0f;

#pragma unroll
        for (int tap = 0; tap < 9; tap++) {
            const int dy = tap / 3 - 1, dx = tap % 3 - 1;
            if (COUTP == 16) {
                float4 vb[NB];
#pragma unroll
                for (int nb = 0; nb < NB; nb++)
                    vb[nb] = *(const float4*)(w2 + (tap * COUT + nb * 8 + g) * 16 + 4 * t);
#pragma unroll
                for (int r = 0; r < 2; r++) {
                    int prow = (wr0 + r + dy + 1) * 18 + dx + 1;
                    float4 va0 = *(const float4*)(s_mid + (prow + g) * 16 + 4 * t);
                    float4 va1 = *(const float4*)(s_mid + (prow + g + 8) * 16 + 4 * t);
#pragma unroll
                    for (int nb = 0; nb < NB; nb++) {
                        mma8(acc[r][nb], U(va0.x), U(va1.x), U(va0.y), U(va1.y), vb[nb].x, vb[nb].y);
                        mma8(acc[r][nb], U(va0.z), U(va1.z), U(va0.w), U(va1.w), vb[nb].z, vb[nb].w);
                    }
                }
            } else {
                const int ppar = (dx + 1 + g) & 1;
#pragma unroll
                for (int kb = 0; kb < 2; kb++) {
                    float4 vb[NB];
#pragma unroll
                    for (int nb = 0; nb < NB; nb++)
                        vb[nb] = *(const float4*)(w2 + (tap * COUT + nb * 8 + g) * 32 + 4 * t + 16 * kb);
                    const int koff = 4 * t + (((kb ^ ppar) & 1) << 4);
#pragma unroll
                    for (int r = 0; r < 2; r++) {
                        int prow = (wr0 + r + dy + 1) * 18 + dx + 1;
                        float4 va0 = *(const float4*)(s_mid + (prow + g) * 32 + koff);
                        float4 va1 = *(const float4*)(s_mid + (prow + g + 8) * 32 + koff);
#pragma unroll
                        for (int nb = 0; nb < NB; nb++) {
                            mma8(acc[r][nb], U(va0.x), U(va1.x), U(va0.y), U(va1.y), vb[nb].x, vb[nb].y);
                            mma8(acc[r][nb], U(va0.z), U(va1.z), U(va0.w), U(va1.w), vb[nb].z, vb[nb].w);
                        }
                    }
                }
            }
        }

        // epilogue: bias + resid (+relu), NHWC float2 stores
#pragma unroll
        for (int r = 0; r < 2; r++) {
            int oy = by + wr0 + r;
            long rowbase = (long)(n * H + oy) * W;
#pragma unroll
            for (int nb = 0; nb < NB; nb++) {
                int co = nb * 8 + 2 * t;
                float bv0 = b2v[co], bv1 = b2v[co + 1];
                long i0 = (rowbase + bx + g) * COUT + co;
                long i1 = (rowbase + bx + g + 8) * COUT + co;
                float2 r0 = *(const float2*)(resid + i0);
                float2 r1 = *(const float2*)(resid + i1);
                float2 v0 = make_float2(acc[r][nb][0] + bv0 + r0.x, acc[r][nb][1] + bv1 + r0.y);
                float2 v1 = make_float2(acc[r][nb][2] + bv0 + r1.x, acc[r][nb][3] + bv1 + r1.y);
                if (RELU_OUT) {
                    v0.x = fmaxf(v0.x, 0.0f); v0.y = fmaxf(v0.y, 0.0f);
                    v1.x = fmaxf(v1.x, 0.0f); v1.y = fmaxf(v1.y, 0.0f);
                }
                *(float2*)(out + i0) = v0;
                *(float2*)(out + i1) = v1;
            }
        }
    }
}

// ---------------- CBAM ----------------
__global__ void cbam_ca_nhwc(const float* __restrict__ x, const float* __restrict__ fc1,
                             const float* __restrict__ fc2, float* __restrict__ ca) {
    int n = blockIdx.x, tid = threadIdx.x;
    int g = tid >> 5, c = tid & 31;
    __shared__ float rs[8][32], rm[8][32], s_mean[32], s_max[32], s_h[8];
    float sm = 0.0f, mx = -3.4e38f;
    for (int p = g; p < 256; p += 8) {
        float v = x[((long)n * 256 + p) * 32 + c];
        sm += v; mx = fmaxf(mx, v);
    }
    rs[g][c] = sm; rm[g][c] = mx;
    __syncthreads();
    if (tid < 32) {
        float s = 0.0f, m = -3.4e38f;
        for (int q = 0; q < 8; q++) { s += rs[q][tid]; m = fmaxf(m, rm[q][tid]); }
        s_mean[tid] = s * (1.0f / 256.0f); s_max[tid] = m;
    }
    __syncthreads();
    if (tid < 8) {
        float hm = 0.0f, hx = 0.0f;
        for (int k = 0; k < 32; k++) {
            float wv = fc1[tid * 32 + k];
            hm += s_mean[k] * wv; hx += s_max[k] * wv;
        }
        s_h[tid] = fmaxf(hm, 0.0f) + fmaxf(hx, 0.0f);
    }
    __syncthreads();
    if (tid < 32) {
        float o = 0.0f;
        for (int j = 0; j < 8; j++) o += s_h[j] * fc2[tid * 8 + j];
        ca[n * 32 + tid] = sigf(o);
    }
}

__global__ void cbam_apply_nhwc(float* x, const float* __restrict__ ca, float* __restrict__ sp) {
    int n = blockIdx.x, p = threadIdx.x;
    __shared__ float s_ca[32];
    if (p < 32) s_ca[p] = ca[n * 32 + p];
    __syncthreads();
    float* base = x + ((long)n * 256 + p) * 32;
    float sum = 0.0f, mx = -3.4e38f;
#pragma unroll
    for (int c = 0; c < 32; c++) {
        float v = base[c] * s_ca[c];
        base[c] = v;
        sum += v; mx = fmaxf(mx, v);
    }
    sp[(long)n * 512 + p] = sum * (1.0f / 32.0f);
    sp[(long)n * 512 + 256 + p] = mx;
}

__global__ void cbam_sa_nhwc(float* x, const float* __restrict__ sp, const float* __restrict__ spw) {
    int n = blockIdx.x, p = threadIdx.x;
    int oy = p >> 4, ox = p & 15;
    __shared__ float s_sp[512], s_w[98];
    s_sp[p] = sp[(long)n * 512 + p];
    s_sp[256 + p] = sp[(long)n * 512 + 256 + p];
    if (p < 98) s_w[p] = spw[p];
    __syncthreads();
    float a = 0.0f;
#pragma unroll
    for (int ci = 0; ci < 2; ci++)
        for (int ky = 0; ky < 7; ky++) {
            int y = oy + ky - 3;
            if (y < 0 || y >= 16) continue;
            for (int kx = 0; kx < 7; kx++) {
                int xx = ox + kx - 3;
                if (xx < 0 || xx >= 16) continue;
                a = fmaf(s_sp[ci * 256 + y * 16 + xx], s_w[(ci * 7 + ky) * 7 + kx], a);
            }
        }
    float sa = sigf(a);
    float* base = x + ((long)n * 256 + p) * 32;
#pragma unroll
    for (int c = 0; c < 32; c++) base[c] *= sa;
}

// permute fc_w[n][c*256+p] -> g_fcwT[n][p*32+c]
__global__ void fcw_permute(const float* __restrict__ w, float* __restrict__ wt) {
    int i = blockIdx.x * 256 + threadIdx.x;
    if (i >= 256 * 8192) return;
    int n = i >> 13;
    int r = i & 8191;
    int c = r >> 8, p = r & 255;
    wt[(n << 13) + p * 32 + c] = w[i];
}

// ---------------- tf32 MMA GEMM: C[M,N] = A[M,K]@B[N,K]^T + bias ----------
template <int RELU>
__global__ __launch_bounds__(256) void gemm_mma_kernel(
    const float* __restrict__ A, const float* __restrict__ B,
    const float* __restrict__ bias, float* __restrict__ C,
    int M, int N, int K) {
    __shared__ float sA[64 * 36], sB[64 * 36];
    const int tid = threadIdx.x;
    const int bm = blockIdx.y * 64, bn = blockIdx.x * 64;
    const int warp = tid >> 5, lane = tid & 31, g = lane >> 2, t = lane & 3;
    const int wm = warp >> 1, wn = warp & 1;
    const int lr = tid >> 2, lc = (tid & 3) * 8;

    float acc[4][4];
#pragma unroll
    for (int i = 0; i < 4; i++)
#pragma unroll
        for (int q = 0; q < 4; q++) acc[i][q] = 0.0f;

    for (int k0 = 0; k0 < K; k0 += 32) {
        float4 va0 = *(const float4*)(A + (long)(bm + lr) * K + k0 + lc);
        float4 va1 = *(const float4*)(A + (long)(bm + lr) * K + k0 + lc + 4);
        float4 vb0 = *(const float4*)(B + (long)(bn + lr) * K + k0 + lc);
        float4 vb1 = *(const float4*)(B + (long)(bn + lr) * K + k0 + lc + 4);
        float* pa = sA + lr * 36 + lc;
        float* pb = sB + lr * 36 + lc;
        pa[0] = tf32f(va0.x); pa[1] = tf32f(va0.y); pa[2] = tf32f(va0.z); pa[3] = tf32f(va0.w);
        pa[4] = tf32f(va1.x); pa[5] = tf32f(va1.y); pa[6] = tf32f(va1.z); pa[7] = tf32f(va1.w);
        pb[0] = tf32f(vb0.x); pb[1] = tf32f(vb0.y); pb[2] = tf32f(vb0.z); pb[3] = tf32f(vb0.w);
        pb[4] = tf32f(vb1.x); pb[5] = tf32f(vb1.y); pb[6] = tf32f(vb1.z); pb[7] = tf32f(vb1.w);
        __syncthreads();
#pragma unroll
        for (int ks = 0; ks < 4; ks++) {
            const int k = ks * 8;
            const int r0 = wm * 16 + g;
            unsigned a0 = U(sA[r0 * 36 + k + t]),       a1 = U(sA[(r0 + 8) * 36 + k + t]);
            unsigned a2 = U(sA[r0 * 36 + k + t + 4]),   a3 = U(sA[(r0 + 8) * 36 + k + t + 4]);
#pragma unroll
            for (int nt = 0; nt < 4; nt++) {
                int nr = wn * 32 + nt * 8 + g;
                mma8(acc[nt], a0, a1, a2, a3, sB[nr * 36 + k + t], sB[nr * 36 + k + t + 4]);
            }
        }
        __syncthreads();
    }
#pragma unroll
    for (int nt = 0; nt < 4; nt++) {
        int n0 = bn + wn * 32 + nt * 8 + 2 * t;
        int m0 = bm + wm * 16 + g;
        float b0 = bias[n0], b1 = bias[n0 + 1];
        float v00 = acc[nt][0] + b0, v01 = acc[nt][1] + b1;
        float v10 = acc[nt][2] + b0, v11 = acc[nt][3] + b1;
        if (RELU) {
            v00 = fmaxf(v00, 0.0f); v01 = fmaxf(v01, 0.0f);
            v10 = fmaxf(v10, 0.0f); v11 = fmaxf(v11, 0.0f);
        }
        C[(long)m0 * N + n0] = v00;       C[(long)m0 * N + n0 + 1] = v01;
        C[(long)(m0 + 8) * N + n0] = v10; C[(long)(m0 + 8) * N + n0 + 1] = v11;
    }
}

// ---------------- GRU scan ----------------
__global__ void gru_scan_kernel(const float* __restrict__ gi, const float* __restrict__ done,
                                const float* __restrict__ h0, const float* __restrict__ whh,
                                const float* __restrict__ bhh, float* __restrict__ hidden) {
    extern __shared__ float sm[];
    float* s_whh = sm;
    float* s_gh = sm + 128 * 384;
    float* s_h = s_gh + 384;
    float* s_hm = s_h + 128;
    int b = blockIdx.x, j = threadIdx.x;

    for (int i = j; i < 384 * 128; i += 384) {
        int jj = i >> 7, k = i & 127;
        s_whh[k * 384 + jj] = whh[i];
    }
    if (j < 128) s_h[j] = h0[b * 128 + j];
    __syncthreads();

    float bh = bhh[j];
    for (int t = 0; t < 64; t++) {
        float dt = done[t * 8 + b];
        if (j < 128) s_hm[j] = (1.0f - dt) * s_h[j];
        __syncthreads();
        float acc = bh;
#pragma unroll 8
        for (int k = 0; k < 128; k++) acc = fmaf(s_hm[k], s_whh[k * 384 + j], acc);
        s_gh[j] = acc;
        __syncthreads();
        if (j < 128) {
            const float* gr = gi + (long)(t * 8 + b) * 384;
            float r = sigf(gr[j] + s_gh[j]);
            float z = sigf(gr[128 + j] + s_gh[128 + j]);
            float nn = tanhf(gr[256 + j] + r * s_gh[256 + j]);
            float hn = (1.0f - z) * nn + z * s_hm[j];
            s_h[j] = hn;
            hidden[(long)(t * 8 + b) * 128 + j] = hn;
        }
        __syncthreads();
    }
}

// ---------------- actor/critic heads ----------------
__global__ void heads_kernel(const float* __restrict__ hidden, const float* __restrict__ aw,
                             const float* __restrict__ ab, const float* __restrict__ cw,
                             const float* __restrict__ cb, float* __restrict__ out) {
    int row = blockIdx.x, t = threadIdx.x;
    __shared__ float s_h[128];
    s_h[t] = hidden[(long)row * 128 + t];
    __syncthreads();
    if (t < 4) {
        const float* w = (t < 3) ? (aw + t * 128) : cw;
        float s = (t < 3) ? ab[t] : cb[0];
        for (int k = 0; k < 128; k++) s = fmaf(s_h[k], w[k], s);
        out[row * 4 + t] = s;
    }
}

// ---------------- host-side launch helpers ----------------
template <int CIN, int COUT, bool RELU_IN, int MODE, bool RELU_OUT, bool NCHW>
static void launch_fused(const float* in, const float* w1, const float* b1,
                         const float* w2, const float* b2,
                         float* out, const float* resid, int H, int W) {
    constexpr int CINP = (CIN <= 8) ? 8 : ((CIN <= 16) ? 16 : 32);
    constexpr int COUTP = (COUT <= 8) ? 8 : ((COUT <= 16) ? 16 : 32);
    constexpr int MSTR = (MODE == 0) ? COUT : COUTP;
    int smem = (400 * CINP + 324 * MSTR) * 4;
    auto kfn = conv_fused_kernel<CIN, COUT, RELU_IN, MODE, RELU_OUT, NCHW>;
    cudaFuncSetAttribute(kfn, cudaFuncAttributeMaxDynamicSharedMemorySize, smem);
    dim3 grid(W / 16, H / 16, 512);
    kfn<<<grid, 256, smem>>>(in, w1, b1, w2, b2, out, resid, H, W);
}

extern "C" void kernel_launch(void* const* d_in, const int* in_sizes, int n_in,
                              void* d_out, int out_size) {
    (void)in_sizes; (void)n_in; (void)out_size;
    const float* x        = (const float*)d_in[0];
    const float* done     = (const float*)d_in[1];
    const float* grustate = (const float*)d_in[2];
    const float* s0_cw = (const float*)d_in[3];
    const float* s0_cb = (const float*)d_in[4];
    const float* s0_rw = (const float*)d_in[5];
    const float* s0_rb = (const float*)d_in[6];
    const float* s1_cw = (const float*)d_in[7];
    const float* s1_cb = (const float*)d_in[8];
    const float* s1_rw = (const float*)d_in[9];
    const float* s1_rb = (const float*)d_in[10];
    const float* s2_cw = (const float*)d_in[11];
    const float* s2_cb = (const float*)d_in[12];
    const float* s2_rw = (const float*)d_in[13];
    const float* s2_rb = (const float*)d_in[14];
    const float* cbam_fc1 = (const float*)d_in[15];
    const float* cbam_fc2 = (const float*)d_in[16];
    const float* cbam_spw = (const float*)d_in[17];
    const float* fc_w  = (const float*)d_in[18];
    const float* fc_b  = (const float*)d_in[19];
    const float* gwih  = (const float*)d_in[20];
    const float* gwhh  = (const float*)d_in[21];
    const float* gbih  = (const float*)d_in[22];
    const float* gbhh  = (const float*)d_in[23];
    const float* aw    = (const float*)d_in[24];
    const float* ab    = (const float*)d_in[25];
    const float* cw    = (const float*)d_in[26];
    const float* cb    = (const float*)d_in[27];
    float* out = (float*)d_out;

    float *X, *O, *CA, *SP, *FEAT, *GI, *HID, *FCWT, *WP;
    cudaGetSymbolAddress((void**)&X, g_X);
    cudaGetSymbolAddress((void**)&O, g_O);
    cudaGetSymbolAddress((void**)&CA, g_ca);
    cudaGetSymbolAddress((void**)&SP, g_sp);
    cudaGetSymbolAddress((void**)&FEAT, g_feat);
    cudaGetSymbolAddress((void**)&GI, g_gi);
    cudaGetSymbolAddress((void**)&HID, g_hid);
    cudaGetSymbolAddress((void**)&FCWT, g_fcwT);
    cudaGetSymbolAddress((void**)&WP, g_wperm);

    const int OFF_S0C = 0;
    const int OFF_S0R = 1152;
    const int OFF_S1C = 10368;
    const int OFF_S1R = 14976;
    const int OFF_S2C = 51840;
    const int OFF_S2R = 61056;

    wperm_all_kernel<<<(97920 + 255) / 256, 256>>>(s0_cw, s0_rw, s1_cw, s1_rw, s2_cw, s2_rw, WP);
    fcw_permute<<<(256 * 8192 + 255) / 256, 256>>>(fc_w, FCWT);

    // ---- stage 0: head 6->16 @128 + pool -> X(64,64,16); 2 fused resblocks ----
    launch_fused<6, 16, false, 0, false, true>(x, WP + OFF_S0C, s0_cb, WP + OFF_S0C, s0_cb, X, nullptr, 128, 128);
    launch_fused<16, 16, true, 1, false, false>(X, WP + OFF_S0R + 0 * 2304, s0_rb + 0,
                                                WP + OFF_S0R + 1 * 2304, s0_rb + 16, O, X, 64, 64);
    launch_fused<16, 16, true, 1, false, false>(O, WP + OFF_S0R + 2 * 2304, s0_rb + 32,
                                                WP + OFF_S0R + 3 * 2304, s0_rb + 48, X, O, 64, 64);

    // ---- stage 1: head 16->32 @64 + pool -> O(32,32,32); 2 fused resblocks ----
    launch_fused<16, 32, false, 0, false, false>(X, WP + OFF_S1C, s1_cb, WP + OFF_S1C, s1_cb, O, nullptr, 64, 64);
    launch_fused<32, 32, true, 1, false, false>(O, WP + OFF_S1R + 0 * 9216, s1_rb + 0,
                                                WP + OFF_S1R + 1 * 9216, s1_rb + 32, X, O, 32, 32);
    launch_fused<32, 32, true, 1, false, false>(X, WP + OFF_S1R + 2 * 9216, s1_rb + 64,
                                                WP + OFF_S1R + 3 * 9216, s1_rb + 96, O, X, 32, 32);

    // ---- stage 2: head 32->32 @32 + pool -> X(16,16,32); 2 fused resblocks ----
    launch_fused<32, 32, false, 0, false, false>(O, WP + OFF_S2C, s2_cb, WP + OFF_S2C, s2_cb, X, nullptr, 32, 32);
    launch_fused<32, 32, true, 1, false, false>(X, WP + OFF_S2R + 0 * 9216, s2_rb + 0,
                                                WP + OFF_S2R + 1 * 9216, s2_rb + 32, O, X, 16, 16);
    launch_fused<32, 32, true, 1, true, false>(O, WP + OFF_S2R + 2 * 9216, s2_rb + 64,
                                               WP + OFF_S2R + 3 * 9216, s2_rb + 96, X, O, 16, 16);

    // ---- CBAM (NHWC, on X) ----
    cbam_ca_nhwc<<<512, 256>>>(X, cbam_fc1, cbam_fc2, CA);
    cbam_apply_nhwc<<<512, 256>>>(X, CA, SP);
    cbam_sa_nhwc<<<512, 256>>>(X, SP, cbam_spw);

    // ---- FC 8192->256 (+relu) and GRU input-gate GEMM, tf32 MMA ----
    gemm_mma_kernel<1><<<dim3(256 / 64, 512 / 64), 256>>>(X, FCWT, fc_b, FEAT, 512, 256, 8192);
    gemm_mma_kernel<0><<<dim3(384 / 64, 512 / 64), 256>>>(FEAT, gwih, gbih, GI, 512, 384, 256);

    // ---- GRU sequential scan ----
    {
        int smem = (128 * 384 + 384 + 128 + 128) * 4;
        cudaFuncSetAttribute(gru_scan_kernel, cudaFuncAttributeMaxDynamicSharedMemorySize, smem);
        gru_scan_kernel<<<8, 384, smem>>>(GI, done, grustate, gwhh, gbhh, HID);
    }

    // ---- actor / critic heads -> (512, 4) ----
    heads_kernel<<<512, 128>>>(HID, aw, ab, cw, cb, out);
}

// round 8
// speedup vs baseline: 2.4279x; 1.3214x over previous
#include <cuda_runtime.h>
#include <cuda_fp16.h>
#include <math.h>

// ---------------- scratch (device globals; no allocations) ----------------
__device__ float g_X[33554432];    // stage state (NHWC)
__device__ float g_O[33554432];    // stage temp (NHWC)
__device__ float g_ca[512 * 32];
__device__ float g_sp[512 * 2 * 256];
__device__ float g_feat[512 * 256];
__device__ float g_gi[512 * 384];
__device__ float g_hid[512 * 128];
__device__ float g_fcwT[256 * 8192];     // fc_w permuted to NHWC-k order
__device__ __half2 g_wperm2[49152];      // all conv weights, fp16 pairs [tap][co][pslot]

__device__ __forceinline__ float sigf(float x) { return 1.0f / (1.0f + expf(-x)); }

__device__ __forceinline__ unsigned tf32u(float x) {
    unsigned r;
    asm("cvt.rna.tf32.f32 %0, %1;" : "=r"(r) : "f"(x));
    return r;
}
__device__ __forceinline__ float tf32f(float x) { return __uint_as_float(tf32u(x)); }

// tf32 k8 MMA (kept for the FC/GRU GEMM)
__device__ __forceinline__ void mma8(float* c, unsigned a0, unsigned a1, unsigned a2, unsigned a3,
                                     float b0f, float b1f) {
    unsigned b0 = __float_as_uint(b0f), b1 = __float_as_uint(b1f);
    asm volatile(
        "mma.sync.aligned.m16n8k8.row.col.f32.tf32.tf32.f32 "
        "{%0,%1,%2,%3},{%4,%5,%6,%7},{%8,%9},{%0,%1,%2,%3};"
        : "+f"(c[0]), "+f"(c[1]), "+f"(c[2]), "+f"(c[3])
        : "r"(a0), "r"(a1), "r"(a2), "r"(a3), "r"(b0), "r"(b1));
}
// fp16 MMAs with fp32 accumulate
__device__ __forceinline__ void mma16h(float* c, unsigned a0, unsigned a1, unsigned a2, unsigned a3,
                                       unsigned b0, unsigned b1) {
    asm volatile(
        "mma.sync.aligned.m16n8k16.row.col.f32.f16.f16.f32 "
        "{%0,%1,%2,%3},{%4,%5,%6,%7},{%8,%9},{%0,%1,%2,%3};"
        : "+f"(c[0]), "+f"(c[1]), "+f"(c[2]), "+f"(c[3])
        : "r"(a0), "r"(a1), "r"(a2), "r"(a3), "r"(b0), "r"(b1));
}
__device__ __forceinline__ void mma8h(float* c, unsigned a0, unsigned a1, unsigned b0) {
    asm volatile(
        "mma.sync.aligned.m16n8k8.row.col.f32.f16.f16.f32 "
        "{%0,%1,%2,%3},{%4,%5},{%6},{%0,%1,%2,%3};"
        : "+f"(c[0]), "+f"(c[1]), "+f"(c[2]), "+f"(c[3])
        : "r"(a0), "r"(a1), "r"(b0));
}
#define U(x) __float_as_uint(x)

// pair-slot permutation: lane t's K16 fragment pairs {t, t+4} (and {t+8,t+12}) contiguous
__device__ __forceinline__ int pslot(int p, int PAIRS) {
    if (PAIRS == 4)  return p;
    if (PAIRS == 8)  return 2 * (p & 3) + (p >> 2);
    return 4 * (p & 3) + (p >> 2);
}

// ---------------- fused weight permute prepass -> fp16 pairs ----------
__global__ void wperm_all_kernel(const float* __restrict__ s0c, const float* __restrict__ s0r,
                                 const float* __restrict__ s1c, const float* __restrict__ s1r,
                                 const float* __restrict__ s2c, const float* __restrict__ s2r,
                                 __half2* __restrict__ dst) {
    int i = blockIdx.x * 256 + threadIdx.x;
    if (i >= 48960) return;
    const float* src; int CIN, PAIRS, COUT, base;
    if (i < 576)        { src = s0c; CIN = 6;  PAIRS = 4;  COUT = 16; base = 0; }
    else if (i < 5184)  { src = s0r; CIN = 16; PAIRS = 8;  COUT = 16; base = 576; }
    else if (i < 7488)  { src = s1c; CIN = 16; PAIRS = 8;  COUT = 32; base = 5184; }
    else if (i < 25920) { src = s1r; CIN = 32; PAIRS = 16; COUT = 32; base = 7488; }
    else if (i < 30528) { src = s2c; CIN = 32; PAIRS = 16; COUT = 32; base = 25920; }
    else                { src = s2r; CIN = 32; PAIRS = 16; COUT = 32; base = 30528; }
    int li = i - base;
    int tap = li % 9; int r = li / 9;
    int p = r % PAIRS; r /= PAIRS;
    int co = r % COUT; int cv = r / COUT;
    int ci0 = 2 * p, ci1 = 2 * p + 1;
    float v0 = (ci0 < CIN) ? src[((cv * COUT + co) * CIN + ci0) * 9 + tap] : 0.0f;
    float v1 = (ci1 < CIN) ? src[((cv * COUT + co) * CIN + ci1) * 9 + tap] : 0.0f;
    dst[base + cv * 9 * COUT * PAIRS + (tap * COUT + co) * PAIRS + pslot(p, PAIRS)] =
        __floats2half2_rn(v0, v1);
}

// ---------------- fused conv kernel (fp16 MMA) ------------------------------
// MODE 0: conv (18x18 region) -> maxpool 3x3 s2 -> out 8x8xCOUT per 16x16 tile.
// MODE 1: conv1 (18x18) -> relu -> conv2 (16x16) + resid (+relu) -> out.
template <int CIN, int COUT, bool RELU_IN, int MODE, bool RELU_OUT, bool NCHW>
__global__ __launch_bounds__(256) void conv_fused_kernel(
    const float* __restrict__ in, const __half2* __restrict__ w1,
    const float* __restrict__ b1v, const __half2* __restrict__ w2,
    const float* __restrict__ b2v, float* __restrict__ out,
    const float* __restrict__ resid, int H, int W) {
    constexpr int CINP = (CIN <= 8) ? 8 : ((CIN <= 16) ? 16 : 32);
    constexpr int PAIRS = CINP / 2;         // 4 / 8 / 16
    constexpr int POP = COUT / 2;           // mid pairs for MODE1 (COUT = 16 or 32)
    constexpr int NB = COUT / 8;
    constexpr int IN_W = 400 * PAIRS;       // 32-bit words (half2) for input halo
    constexpr int MID_W = (MODE == 0) ? 324 * COUT : 324 * POP;

    extern __shared__ __half2 smh[];
    __half2* s_in2 = smh;
    float* s_midf = (float*)(smh + IN_W);
    __half2* s_mid2 = smh + IN_W;
    unsigned* sm32 = (unsigned*)smh;

    const int tid = threadIdx.x;
    const int n = blockIdx.z;
    const int by = blockIdx.y * 16, bx = blockIdx.x * 16;

    for (int i = tid; i < IN_W + MID_W; i += 256) sm32[i] = 0u;
    __syncthreads();

    // ---- stage 20x20 input halo as fp16 pairs ----
    if (NCHW) {  // head stage 0: CIN=6, PAIRS=4, pslot identity -> half index pix*8+ci
        __half* s_inh = (__half*)s_in2;
        for (int i = tid; i < 400 * CIN; i += 256) {
            int ci = i / 400, pix = i - ci * 400;
            int iy = pix / 20, ix = pix - iy * 20;
            int gy = by + iy - 2, gx = bx + ix - 2;
            if (gy >= 0 && gy < H && gx >= 0 && gx < W) {
                float v = in[((long)(n * CIN + ci) * H + gy) * W + gx];
                if (RELU_IN) v = fmaxf(v, 0.0f);
                s_inh[pix * 8 + ci] = __float2half_rn(v);
            }
        }
    } else {
        constexpr int C4 = CIN / 4;
        for (int i = tid; i < 400 * C4; i += 256) {
            int pix = i / C4, c4 = i - pix * C4;
            int iy = pix / 20, ix = pix - iy * 20;
            int gy = by + iy - 2, gx = bx + ix - 2;
            if (gy >= 0 && gy < H && gx >= 0 && gx < W) {
                float4 v = *(const float4*)(in + ((long)(n * H + gy) * W + gx) * CIN + 4 * c4);
                if (RELU_IN) {
                    v.x = fmaxf(v.x, 0.0f); v.y = fmaxf(v.y, 0.0f);
                    v.z = fmaxf(v.z, 0.0f); v.w = fmaxf(v.w, 0.0f);
                }
                s_in2[pix * PAIRS + pslot(2 * c4, PAIRS)] = __floats2half2_rn(v.x, v.y);
                s_in2[pix * PAIRS + pslot(2 * c4 + 1, PAIRS)] = __floats2half2_rn(v.z, v.w);
            }
        }
    }
    __syncthreads();

    const int warp = tid >> 5, lane = tid & 31, g = lane >> 2, t = lane & 3;
    const unsigned* su = (const unsigned*)s_in2;
    const unsigned* w1u = (const unsigned*)w1;

    // ---- conv1 over 18x18 region: 3 M16 tiles per warp ----
    float acc1[3][NB][4];
#pragma unroll
    for (int s = 0; s < 3; s++)
#pragma unroll
        for (int nb = 0; nb < NB; nb++)
#pragma unroll
            for (int q = 0; q < 4; q++) acc1[s][nb][q] = 0.0f;

    int base0[3], base1[3];
#pragma unroll
    for (int s = 0; s < 3; s++) {
        int tt = warp + 8 * s;
        int p0 = tt * 16 + g, p1 = p0 + 8;
        int q0 = p0 > 323 ? 323 : p0, q1 = p1 > 323 ? 323 : p1;
        base0[s] = (q0 / 18 + 1) * 20 + (q0 % 18 + 1);
        base1[s] = (q1 / 18 + 1) * 20 + (q1 % 18 + 1);
    }

#pragma unroll
    for (int tap = 0; tap < 9; tap++) {
        const int dy = tap / 3 - 1, dx = tap % 3 - 1;
        const int off = dy * 20 + dx;
        if (PAIRS == 4) {          // k8 MMA
            unsigned vb[NB];
#pragma unroll
            for (int nb = 0; nb < NB; nb++)
                vb[nb] = w1u[(tap * COUT + nb * 8 + g) * 4 + t];
#pragma unroll
            for (int s = 0; s < 3; s++) {
                unsigned a0 = su[(base0[s] + off) * 4 + t];
                unsigned a1 = su[(base1[s] + off) * 4 + t];
#pragma unroll
                for (int nb = 0; nb < NB; nb++) mma8h(acc1[s][nb], a0, a1, vb[nb]);
            }
        } else if (PAIRS == 8) {   // one k16 MMA
            uint2 vb[NB];
#pragma unroll
            for (int nb = 0; nb < NB; nb++)
                vb[nb] = *(const uint2*)(w1u + (tap * COUT + nb * 8 + g) * 8 + 2 * t);
#pragma unroll
            for (int s = 0; s < 3; s++) {
                uint2 va0 = *(const uint2*)(su + (base0[s] + off) * 8 + 2 * t);
                uint2 va1 = *(const uint2*)(su + (base1[s] + off) * 8 + 2 * t);
#pragma unroll
                for (int nb = 0; nb < NB; nb++)
                    mma16h(acc1[s][nb], va0.x, va1.x, va0.y, va1.y, vb[nb].x, vb[nb].y);
            }
        } else {                   // PAIRS==16: two k16 MMAs
            uint4 vb[NB];
#pragma unroll
            for (int nb = 0; nb < NB; nb++)
                vb[nb] = *(const uint4*)(w1u + (tap * COUT + nb * 8 + g) * 16 + 4 * t);
#pragma unroll
            for (int s = 0; s < 3; s++) {
                uint4 va0 = *(const uint4*)(su + (base0[s] + off) * 16 + 4 * t);
                uint4 va1 = *(const uint4*)(su + (base1[s] + off) * 16 + 4 * t);
#pragma unroll
                for (int nb = 0; nb < NB; nb++) {
                    mma16h(acc1[s][nb], va0.x, va1.x, va0.y, va1.y, vb[nb].x, vb[nb].y);
                    mma16h(acc1[s][nb], va0.z, va1.z, va0.w, va1.w, vb[nb].z, vb[nb].w);
                }
            }
        }
    }

    // ---- store conv1 results to s_mid ----
#pragma unroll
    for (int s = 0; s < 3; s++) {
        int pbase = (warp + 8 * s) * 16 + g;
#pragma unroll
        for (int half = 0; half < 2; half++) {
            int p = pbase + 8 * half;
            if (p < 324) {
                int r = p / 18, c = p - r * 18;
                int gy = by - 1 + r, gx = bx - 1 + c;
                if (gy >= 0 && gy < H && gx >= 0 && gx < W) {
#pragma unroll
                    for (int nb = 0; nb < NB; nb++) {
                        int co = nb * 8 + 2 * t;
                        float v0 = acc1[s][nb][2 * half + 0] + b1v[co];
                        float v1 = acc1[s][nb][2 * half + 1] + b1v[co + 1];
                        if (MODE == 0) {
                            s_midf[p * COUT + co] = v0;
                            s_midf[p * COUT + co + 1] = v1;
                        } else {
                            int pr = nb * 4 + t;
                            s_mid2[p * POP + pslot(pr, POP)] =
                                __floats2half2_rn(fmaxf(v0, 0.0f), fmaxf(v1, 0.0f));
                        }
                    }
                }
            }
        }
    }
    __syncthreads();

    if (MODE == 0) {
        // ---- maxpool 3x3 s2 over s_midf -> 8x8 x COUT ----
        int H2 = H >> 1, W2 = W >> 1;
        for (int o = tid; o < 64 * COUT; o += 256) {
            int co = o % COUT; int pp = o / COUT;
            int ly = pp >> 3, lx = pp & 7;
            float m = -3.4e38f;
#pragma unroll
            for (int dy = 0; dy < 3; dy++) {
                int r = 2 * ly + dy;
                int gy = by - 1 + r;
                if (gy < 0 || gy >= H) continue;
#pragma unroll
                for (int dxx = 0; dxx < 3; dxx++) {
                    int c = 2 * lx + dxx;
                    int gx = bx - 1 + c;
                    if (gx < 0 || gx >= W) continue;
                    m = fmaxf(m, s_midf[(r * 18 + c) * COUT + co]);
                }
            }
            out[(((long)n * H2 + (by / 2 + ly)) * W2 + (bx / 2 + lx)) * COUT + co] = m;
        }
    } else {
        // ---- conv2 16x16 from s_mid2 (18-wide rows, POP pairs) ----
        const unsigned* mu = (const unsigned*)s_mid2;
        const unsigned* w2u = (const unsigned*)w2;
        const int wr0 = warp * 2;
        float acc[2][NB][4];
#pragma unroll
        for (int r = 0; r < 2; r++)
#pragma unroll
            for (int nb = 0; nb < NB; nb++)
#pragma unroll
                for (int q = 0; q < 4; q++) acc[r][nb][q] = 0.0f;

#pragma unroll
        for (int tap = 0; tap < 9; tap++) {
            const int dy = tap / 3 - 1, dx = tap % 3 - 1;
            if (POP == 8) {
                uint2 vb[NB];
#pragma unroll
                for (int nb = 0; nb < NB; nb++)
                    vb[nb] = *(const uint2*)(w2u + (tap * COUT + nb * 8 + g) * 8 + 2 * t);
#pragma unroll
                for (int r = 0; r < 2; r++) {
                    int prow = (wr0 + r + dy + 1) * 18 + dx + 1;
                    uint2 va0 = *(const uint2*)(mu + (prow + g) * 8 + 2 * t);
                    uint2 va1 = *(const uint2*)(mu + (prow + g + 8) * 8 + 2 * t);
#pragma unroll
                    for (int nb = 0; nb < NB; nb++)
                        mma16h(acc[r][nb], va0.x, va1.x, va0.y, va1.y, vb[nb].x, vb[nb].y);
                }
            } else {
                uint4 vb[NB];
#pragma unroll
                for (int nb = 0; nb < NB; nb++)
                    vb[nb] = *(const uint4*)(w2u + (tap * COUT + nb * 8 + g) * 16 + 4 * t);
#pragma unroll
                for (int r = 0; r < 2; r++) {
                    int prow = (wr0 + r + dy + 1) * 18 + dx + 1;
                    uint4 va0 = *(const uint4*)(mu + (prow + g) * 16 + 4 * t);
                    uint4 va1 = *(const uint4*)(mu + (prow + g + 8) * 16 + 4 * t);
#pragma unroll
                    for (int nb = 0; nb < NB; nb++) {
                        mma16h(acc[r][nb], va0.x, va1.x, va0.y, va1.y, vb[nb].x, vb[nb].y);
                        mma16h(acc[r][nb], va0.z, va1.z, va0.w, va1.w, vb[nb].z, vb[nb].w);
                    }
                }
            }
        }

        // epilogue: bias + resid (+relu), NHWC float2 stores
#pragma unroll
        for (int r = 0; r < 2; r++) {
            int oy = by + wr0 + r;
            long rowbase = (long)(n * H + oy) * W;
#pragma unroll
            for (int nb = 0; nb < NB; nb++) {
                int co = nb * 8 + 2 * t;
                float bv0 = b2v[co], bv1 = b2v[co + 1];
                long i0 = (rowbase + bx + g) * COUT + co;
                long i1 = (rowbase + bx + g + 8) * COUT + co;
                float2 r0 = *(const float2*)(resid + i0);
                float2 r1 = *(const float2*)(resid + i1);
                float2 v0 = make_float2(acc[r][nb][0] + bv0 + r0.x, acc[r][nb][1] + bv1 + r0.y);
                float2 v1 = make_float2(acc[r][nb][2] + bv0 + r1.x, acc[r][nb][3] + bv1 + r1.y);
                if (RELU_OUT) {
                    v0.x = fmaxf(v0.x, 0.0f); v0.y = fmaxf(v0.y, 0.0f);
                    v1.x = fmaxf(v1.x, 0.0f); v1.y = fmaxf(v1.y, 0.0f);
                }
                *(float2*)(out + i0) = v0;
                *(float2*)(out + i1) = v1;
            }
        }
    }
}

// ---------------- CBAM ----------------
__global__ void cbam_ca_nhwc(const float* __restrict__ x, const float* __restrict__ fc1,
                             const float* __restrict__ fc2, float* __restrict__ ca) {
    int n = blockIdx.x, tid = threadIdx.x;
    int g = tid >> 5, c = tid & 31;
    __shared__ float rs[8][32], rm[8][32], s_mean[32], s_max[32], s_h[8];
    float sm = 0.0f, mx = -3.4e38f;
    for (int p = g; p < 256; p += 8) {
        float v = x[((long)n * 256 + p) * 32 + c];
        sm += v; mx = fmaxf(mx, v);
    }
    rs[g][c] = sm; rm[g][c] = mx;
    __syncthreads();
    if (tid < 32) {
        float s = 0.0f, m = -3.4e38f;
        for (int q = 0; q < 8; q++) { s += rs[q][tid]; m = fmaxf(m, rm[q][tid]); }
        s_mean[tid] = s * (1.0f / 256.0f); s_max[tid] = m;
    }
    __syncthreads();
    if (tid < 8) {
        float hm = 0.0f, hx = 0.0f;
        for (int k = 0; k < 32; k++) {
            float wv = fc1[tid * 32 + k];
            hm += s_mean[k] * wv; hx += s_max[k] * wv;
        }
        s_h[tid] = fmaxf(hm, 0.0f) + fmaxf(hx, 0.0f);
    }
    __syncthreads();
    if (tid < 32) {
        float o = 0.0f;
        for (int j = 0; j < 8; j++) o += s_h[j] * fc2[tid * 8 + j];
        ca[n * 32 + tid] = sigf(o);
    }
}

__global__ void cbam_apply_nhwc(float* x, const float* __restrict__ ca, float* __restrict__ sp) {
    int n = blockIdx.x, p = threadIdx.x;
    __shared__ float s_ca[32];
    if (p < 32) s_ca[p] = ca[n * 32 + p];
    __syncthreads();
    float* base = x + ((long)n * 256 + p) * 32;
    float sum = 0.0f, mx = -3.4e38f;
#pragma unroll
    for (int c = 0; c < 32; c++) {
        float v = base[c] * s_ca[c];
        base[c] = v;
        sum += v; mx = fmaxf(mx, v);
    }
    sp[(long)n * 512 + p] = sum * (1.0f / 32.0f);
    sp[(long)n * 512 + 256 + p] = mx;
}

__global__ void cbam_sa_nhwc(float* x, const float* __restrict__ sp, const float* __restrict__ spw) {
    int n = blockIdx.x, p = threadIdx.x;
    int oy = p >> 4, ox = p & 15;
    __shared__ float s_sp[512], s_w[98];
    s_sp[p] = sp[(long)n * 512 + p];
    s_sp[256 + p] = sp[(long)n * 512 + 256 + p];
    if (p < 98) s_w[p] = spw[p];
    __syncthreads();
    float a = 0.0f;
#pragma unroll
    for (int ci = 0; ci < 2; ci++)
        for (int ky = 0; ky < 7; ky++) {
            int y = oy + ky - 3;
            if (y < 0 || y >= 16) continue;
            for (int kx = 0; kx < 7; kx++) {
                int xx = ox + kx - 3;
                if (xx < 0 || xx >= 16) continue;
                a = fmaf(s_sp[ci * 256 + y * 16 + xx], s_w[(ci * 7 + ky) * 7 + kx], a);
            }
        }
    float sa = sigf(a);
    float* base = x + ((long)n * 256 + p) * 32;
#pragma unroll
    for (int c = 0; c < 32; c++) base[c] *= sa;
}

// permute fc_w[n][c*256+p] -> g_fcwT[n][p*32+c]
__global__ void fcw_permute(const float* __restrict__ w, float* __restrict__ wt) {
    int i = blockIdx.x * 256 + threadIdx.x;
    if (i >= 256 * 8192) return;
    int n = i >> 13;
    int r = i & 8191;
    int c = r >> 8, p = r & 255;
    wt[(n << 13) + p * 32 + c] = w[i];
}

// ---------------- tf32 MMA GEMM: C[M,N] = A[M,K]@B[N,K]^T + bias ----------
template <int RELU>
__global__ __launch_bounds__(256) void gemm_mma_kernel(
    const float* __restrict__ A, const float* __restrict__ B,
    const float* __restrict__ bias, float* __restrict__ C,
    int M, int N, int K) {
    __shared__ float sA[64 * 36], sB[64 * 36];
    const int tid = threadIdx.x;
    const int bm = blockIdx.y * 64, bn = blockIdx.x * 64;
    const int warp = tid >> 5, lane = tid & 31, g = lane >> 2, t = lane & 3;
    const int wm = warp >> 1, wn = warp & 1;
    const int lr = tid >> 2, lc = (tid & 3) * 8;

    float acc[4][4];
#pragma unroll
    for (int i = 0; i < 4; i++)
#pragma unroll
        for (int q = 0; q < 4; q++) acc[i][q] = 0.0f;

    for (int k0 = 0; k0 < K; k0 += 32) {
        float4 va0 = *(const float4*)(A + (long)(bm + lr) * K + k0 + lc);
        float4 va1 = *(const float4*)(A + (long)(bm + lr) * K + k0 + lc + 4);
        float4 vb0 = *(const float4*)(B + (long)(bn + lr) * K + k0 + lc);
        float4 vb1 = *(const float4*)(B + (long)(bn + lr) * K + k0 + lc + 4);
        float* pa = sA + lr * 36 + lc;
        float* pb = sB + lr * 36 + lc;
        pa[0] = tf32f(va0.x); pa[1] = tf32f(va0.y); pa[2] = tf32f(va0.z); pa[3] = tf32f(va0.w);
        pa[4] = tf32f(va1.x); pa[5] = tf32f(va1.y); pa[6] = tf32f(va1.z); pa[7] = tf32f(va1.w);
        pb[0] = tf32f(vb0.x); pb[1] = tf32f(vb0.y); pb[2] = tf32f(vb0.z); pb[3] = tf32f(vb0.w);
        pb[4] = tf32f(vb1.x); pb[5] = tf32f(vb1.y); pb[6] = tf32f(vb1.z); pb[7] = tf32f(vb1.w);
        __syncthreads();
#pragma unroll
        for (int ks = 0; ks < 4; ks++) {
            const int k = ks * 8;
            const int r0 = wm * 16 + g;
            unsigned a0 = U(sA[r0 * 36 + k + t]),       a1 = U(sA[(r0 + 8) * 36 + k + t]);
            unsigned a2 = U(sA[r0 * 36 + k + t + 4]),   a3 = U(sA[(r0 + 8) * 36 + k + t + 4]);
#pragma unroll
            for (int nt = 0; nt < 4; nt++) {
                int nr = wn * 32 + nt * 8 + g;
                mma8(acc[nt], a0, a1, a2, a3, sB[nr * 36 + k + t], sB[nr * 36 + k + t + 4]);
            }
        }
        __syncthreads();
    }
#pragma unroll
    for (int nt = 0; nt < 4; nt++) {
        int n0 = bn + wn * 32 + nt * 8 + 2 * t;
        int m0 = bm + wm * 16 + g;
        float b0 = bias[n0], b1 = bias[n0 + 1];
        float v00 = acc[nt][0] + b0, v01 = acc[nt][1] + b1;
        float v10 = acc[nt][2] + b0, v11 = acc[nt][3] + b1;
        if (RELU) {
            v00 = fmaxf(v00, 0.0f); v01 = fmaxf(v01, 0.0f);
            v10 = fmaxf(v10, 0.0f); v11 = fmaxf(v11, 0.0f);
        }
        C[(long)m0 * N + n0] = v00;       C[(long)m0 * N + n0 + 1] = v01;
        C[(long)(m0 + 8) * N + n0] = v10; C[(long)(m0 + 8) * N + n0 + 1] = v11;
    }
}

// ---------------- GRU scan ----------------
__global__ void gru_scan_kernel(const float* __restrict__ gi, const float* __restrict__ done,
                                const float* __restrict__ h0, const float* __restrict__ whh,
                                const float* __restrict__ bhh, float* __restrict__ hidden) {
    extern __shared__ float sm[];
    float* s_whh = sm;
    float* s_gh = sm + 128 * 384;
    float* s_h = s_gh + 384;
    float* s_hm = s_h + 128;
    int b = blockIdx.x, j = threadIdx.x;

    for (int i = j; i < 384 * 128; i += 384) {
        int jj = i >> 7, k = i & 127;
        s_whh[k * 384 + jj] = whh[i];
    }
    if (j < 128) s_h[j] = h0[b * 128 + j];
    __syncthreads();

    float bh = bhh[j];
    for (int t = 0; t < 64; t++) {
        float dt = done[t * 8 + b];
        if (j < 128) s_hm[j] = (1.0f - dt) * s_h[j];
        __syncthreads();
        float acc = bh;
#pragma unroll 8
        for (int k = 0; k < 128; k++) acc = fmaf(s_hm[k], s_whh[k * 384 + j], acc);
        s_gh[j] = acc;
        __syncthreads();
        if (j < 128) {
            const float* gr = gi + (long)(t * 8 + b) * 384;
            float r = sigf(gr[j] + s_gh[j]);
            float z = sigf(gr[128 + j] + s_gh[128 + j]);
            float nn = tanhf(gr[256 + j] + r * s_gh[256 + j]);
            float hn = (1.0f - z) * nn + z * s_hm[j];
            s_h[j] = hn;
            hidden[(long)(t * 8 + b) * 128 + j] = hn;
        }
        __syncthreads();
    }
}

// ---------------- actor/critic heads ----------------
__global__ void heads_kernel(const float* __restrict__ hidden, const float* __restrict__ aw,
                             const float* __restrict__ ab, const float* __restrict__ cw,
                             const float* __restrict__ cb, float* __restrict__ out) {
    int row = blockIdx.x, t = threadIdx.x;
    __shared__ float s_h[128];
    s_h[t] = hidden[(long)row * 128 + t];
    __syncthreads();
    if (t < 4) {
        const float* w = (t < 3) ? (aw + t * 128) : cw;
        float s = (t < 3) ? ab[t] : cb[0];
        for (int k = 0; k < 128; k++) s = fmaf(s_h[k], w[k], s);
        out[row * 4 + t] = s;
    }
}

// ---------------- host-side launch helpers ----------------
template <int CIN, int COUT, bool RELU_IN, int MODE, bool RELU_OUT, bool NCHW>
static void launch_fused(const float* in, const __half2* w1, const float* b1,
                         const __half2* w2, const float* b2,
                         float* out, const float* resid, int H, int W) {
    constexpr int CINP = (CIN <= 8) ? 8 : ((CIN <= 16) ? 16 : 32);
    constexpr int PAIRS = CINP / 2;
    constexpr int MID_W = (MODE == 0) ? 324 * COUT : 324 * (COUT / 2);
    int smem = (400 * PAIRS + MID_W) * 4;
    auto kfn = conv_fused_kernel<CIN, COUT, RELU_IN, MODE, RELU_OUT, NCHW>;
    cudaFuncSetAttribute(kfn, cudaFuncAttributeMaxDynamicSharedMemorySize, smem);
    dim3 grid(W / 16, H / 16, 512);
    kfn<<<grid, 256, smem>>>(in, w1, b1, w2, b2, out, resid, H, W);
}

extern "C" void kernel_launch(void* const* d_in, const int* in_sizes, int n_in,
                              void* d_out, int out_size) {
    (void)in_sizes; (void)n_in; (void)out_size;
    const float* x        = (const float*)d_in[0];
    const float* done     = (const float*)d_in[1];
    const float* grustate = (const float*)d_in[2];
    const float* s0_cw = (const float*)d_in[3];
    const float* s0_cb = (const float*)d_in[4];
    const float* s0_rw = (const float*)d_in[5];
    const float* s0_rb = (const float*)d_in[6];
    const float* s1_cw = (const float*)d_in[7];
    const float* s1_cb = (const float*)d_in[8];
    const float* s1_rw = (const float*)d_in[9];
    const float* s1_rb = (const float*)d_in[10];
    const float* s2_cw = (const float*)d_in[11];
    const float* s2_cb = (const float*)d_in[12];
    const float* s2_rw = (const float*)d_in[13];
    const float* s2_rb = (const float*)d_in[14];
    const float* cbam_fc1 = (const float*)d_in[15];
    const float* cbam_fc2 = (const float*)d_in[16];
    const float* cbam_spw = (const float*)d_in[17];
    const float* fc_w  = (const float*)d_in[18];
    const float* fc_b  = (const float*)d_in[19];
    const float* gwih  = (const float*)d_in[20];
    const float* gwhh  = (const float*)d_in[21];
    const float* gbih  = (const float*)d_in[22];
    const float* gbhh  = (const float*)d_in[23];
    const float* aw    = (const float*)d_in[24];
    const float* ab    = (const float*)d_in[25];
    const float* cw    = (const float*)d_in[26];
    const float* cb    = (const float*)d_in[27];
    float* out = (float*)d_out;

    float *X, *O, *CA, *SP, *FEAT, *GI, *HID, *FCWT;
    __half2* WP;
    cudaGetSymbolAddress((void**)&X, g_X);
    cudaGetSymbolAddress((void**)&O, g_O);
    cudaGetSymbolAddress((void**)&CA, g_ca);
    cudaGetSymbolAddress((void**)&SP, g_sp);
    cudaGetSymbolAddress((void**)&FEAT, g_feat);
    cudaGetSymbolAddress((void**)&GI, g_gi);
    cudaGetSymbolAddress((void**)&HID, g_hid);
    cudaGetSymbolAddress((void**)&FCWT, g_fcwT);
    cudaGetSymbolAddress((void**)&WP, g_wperm2);

    // weight offsets in half2 units
    const int OFF_S0C = 0;       // 9*16*4   = 576
    const int OFF_S0R = 576;     // 4 convs of 9*16*8 = 1152 each
    const int OFF_S1C = 5184;    // 9*32*8   = 2304
    const int OFF_S1R = 7488;    // 4 convs of 9*32*16 = 4608 each
    const int OFF_S2C = 25920;   // 4608
    const int OFF_S2R = 30528;   // 4 x 4608

    wperm_all_kernel<<<(48960 + 255) / 256, 256>>>(s0_cw, s0_rw, s1_cw, s1_rw, s2_cw, s2_rw, WP);
    fcw_permute<<<(256 * 8192 + 255) / 256, 256>>>(fc_w, FCWT);

    // ---- stage 0: head 6->16 @128 + pool -> X(64,64,16); 2 fused resblocks ----
    launch_fused<6, 16, false, 0, false, true>(x, WP + OFF_S0C, s0_cb, WP + OFF_S0C, s0_cb, X, nullptr, 128, 128);
    launch_fused<16, 16, true, 1, false, false>(X, WP + OFF_S0R + 0 * 1152, s0_rb + 0,
                                                WP + OFF_S0R + 1 * 1152, s0_rb + 16, O, X, 64, 64);
    launch_fused<16, 16, true, 1, false, false>(O, WP + OFF_S0R + 2 * 1152, s0_rb + 32,
                                                WP + OFF_S0R + 3 * 1152, s0_rb + 48, X, O, 64, 64);

    // ---- stage 1: head 16->32 @64 + pool -> O(32,32,32); 2 fused resblocks ----
    launch_fused<16, 32, false, 0, false, false>(X, WP + OFF_S1C, s1_cb, WP + OFF_S1C, s1_cb, O, nullptr, 64, 64);
    launch_fused<32, 32, true, 1, false, false>(O, WP + OFF_S1R + 0 * 4608, s1_rb + 0,
                                                WP + OFF_S1R + 1 * 4608, s1_rb + 32, X, O, 32, 32);
    launch_fused<32, 32, true, 1, false, false>(X, WP + OFF_S1R + 2 * 4608, s1_rb + 64,
                                                WP + OFF_S1R + 3 * 4608, s1_rb + 96, O, X, 32, 32);

    // ---- stage 2: head 32->32 @32 + pool -> X(16,16,32); 2 fused resblocks ----
    launch_fused<32, 32, false, 0, false, false>(O, WP + OFF_S2C, s2_cb, WP + OFF_S2C, s2_cb, X, nullptr, 32, 32);
    launch_fused<32, 32, true, 1, false, false>(X, WP + OFF_S2R + 0 * 4608, s2_rb + 0,
                                                WP + OFF_S2R + 1 * 4608, s2_rb + 32, O, X, 16, 16);
    launch_fused<32, 32, true, 1, true, false>(O, WP + OFF_S2R + 2 * 4608, s2_rb + 64,
                                               WP + OFF_S2R + 3 * 4608, s2_rb + 96, X, O, 16, 16);

    // ---- CBAM (NHWC, on X) ----
    cbam_ca_nhwc<<<512, 256>>>(X, cbam_fc1, cbam_fc2, CA);
    cbam_apply_nhwc<<<512, 256>>>(X, CA, SP);
    cbam_sa_nhwc<<<512, 256>>>(X, SP, cbam_spw);

    // ---- FC 8192->256 (+relu) and GRU input-gate GEMM, tf32 MMA ----
    gemm_mma_kernel<1><<<dim3(256 / 64, 512 / 64), 256>>>(X, FCWT, fc_b, FEAT, 512, 256, 8192);
    gemm_mma_kernel<0><<<dim3(384 / 64, 512 / 64), 256>>>(FEAT, gwih, gbih, GI, 512, 384, 256);

    // ---- GRU sequential scan ----
    {
        int smem = (128 * 384 + 384 + 128 + 128) * 4;
        cudaFuncSetAttribute(gru_scan_kernel, cudaFuncAttributeMaxDynamicSharedMemorySize, smem);
        gru_scan_kernel<<<8, 384, smem>>>(GI, done, grustate, gwhh, gbhh, HID);
    }

    // ---- actor / critic heads -> (512, 4) ----
    heads_kernel<<<512, 128>>>(HID, aw, ab, cw, cb, out);
}

// round 9
// speedup vs baseline: 2.5724x; 1.0595x over previous
#include <cuda_runtime.h>
#include <cuda_fp16.h>
#include <math.h>

// ---------------- scratch (device globals; no allocations) ----------------
__device__ float g_X[33554432];    // stage state (NHWC)
__device__ float g_O[33554432];    // stage temp (NHWC)
__device__ float g_feat[512 * 256];
__device__ float g_gi[512 * 384];
__device__ float g_hid[512 * 128];
__device__ float g_fcwT[256 * 8192];     // fc_w permuted to NHWC-k order
__device__ __half2 g_wperm2[49152];      // all conv weights, fp16 pairs [tap][co][pslot]

__device__ __forceinline__ float sigf(float x) { return 1.0f / (1.0f + expf(-x)); }

__device__ __forceinline__ unsigned tf32u(float x) {
    unsigned r;
    asm("cvt.rna.tf32.f32 %0, %1;" : "=r"(r) : "f"(x));
    return r;
}
__device__ __forceinline__ float tf32f(float x) { return __uint_as_float(tf32u(x)); }

// tf32 k8 MMA (FC/GRU GEMM)
__device__ __forceinline__ void mma8(float* c, unsigned a0, unsigned a1, unsigned a2, unsigned a3,
                                     float b0f, float b1f) {
    unsigned b0 = __float_as_uint(b0f), b1 = __float_as_uint(b1f);
    asm volatile(
        "mma.sync.aligned.m16n8k8.row.col.f32.tf32.tf32.f32 "
        "{%0,%1,%2,%3},{%4,%5,%6,%7},{%8,%9},{%0,%1,%2,%3};"
        : "+f"(c[0]), "+f"(c[1]), "+f"(c[2]), "+f"(c[3])
        : "r"(a0), "r"(a1), "r"(a2), "r"(a3), "r"(b0), "r"(b1));
}
// fp16 MMAs with fp32 accumulate
__device__ __forceinline__ void mma16h(float* c, unsigned a0, unsigned a1, unsigned a2, unsigned a3,
                                       unsigned b0, unsigned b1) {
    asm volatile(
        "mma.sync.aligned.m16n8k16.row.col.f32.f16.f16.f32 "
        "{%0,%1,%2,%3},{%4,%5,%6,%7},{%8,%9},{%0,%1,%2,%3};"
        : "+f"(c[0]), "+f"(c[1]), "+f"(c[2]), "+f"(c[3])
        : "r"(a0), "r"(a1), "r"(a2), "r"(a3), "r"(b0), "r"(b1));
}
__device__ __forceinline__ void mma8h(float* c, unsigned a0, unsigned a1, unsigned b0) {
    asm volatile(
        "mma.sync.aligned.m16n8k8.row.col.f32.f16.f16.f32 "
        "{%0,%1,%2,%3},{%4,%5},{%6},{%0,%1,%2,%3};"
        : "+f"(c[0]), "+f"(c[1]), "+f"(c[2]), "+f"(c[3])
        : "r"(a0), "r"(a1), "r"(b0));
}
#define U(x) __float_as_uint(x)

__device__ __forceinline__ int pslot(int p, int PAIRS) {
    if (PAIRS == 4)  return p;
    if (PAIRS == 8)  return 2 * (p & 3) + (p >> 2);
    return 4 * (p & 3) + (p >> 2);
}

// ---------------- fused weight permute prepass -> fp16 pairs ----------
__global__ void wperm_all_kernel(const float* __restrict__ s0c, const float* __restrict__ s0r,
                                 const float* __restrict__ s1c, const float* __restrict__ s1r,
                                 const float* __restrict__ s2c, const float* __restrict__ s2r,
                                 __half2* __restrict__ dst) {
    int i = blockIdx.x * 256 + threadIdx.x;
    if (i >= 48960) return;
    const float* src; int CIN, PAIRS, COUT, base;
    if (i < 576)        { src = s0c; CIN = 6;  PAIRS = 4;  COUT = 16; base = 0; }
    else if (i < 5184)  { src = s0r; CIN = 16; PAIRS = 8;  COUT = 16; base = 576; }
    else if (i < 7488)  { src = s1c; CIN = 16; PAIRS = 8;  COUT = 32; base = 5184; }
    else if (i < 25920) { src = s1r; CIN = 32; PAIRS = 16; COUT = 32; base = 7488; }
    else if (i < 30528) { src = s2c; CIN = 32; PAIRS = 16; COUT = 32; base = 25920; }
    else                { src = s2r; CIN = 32; PAIRS = 16; COUT = 32; base = 30528; }
    int li = i - base;
    int tap = li % 9; int r = li / 9;
    int p = r % PAIRS; r /= PAIRS;
    int co = r % COUT; int cv = r / COUT;
    int ci0 = 2 * p, ci1 = 2 * p + 1;
    float v0 = (ci0 < CIN) ? src[((cv * COUT + co) * CIN + ci0) * 9 + tap] : 0.0f;
    float v1 = (ci1 < CIN) ? src[((cv * COUT + co) * CIN + ci1) * 9 + tap] : 0.0f;
    dst[base + cv * 9 * COUT * PAIRS + (tap * COUT + co) * PAIRS + pslot(p, PAIRS)] =
        __floats2half2_rn(v0, v1);
}

// ---------------- fused conv kernel (fp16 MMA) ------------------------------
// MODE 0: conv (18x18 region) -> maxpool 3x3 s2 -> out 8x8xCOUT per 16x16 tile.
// MODE 1: conv1 (18x18) -> relu -> conv2 (16x16) + resid (+relu) -> out.
template <int CIN, int COUT, bool RELU_IN, int MODE, bool RELU_OUT, bool NCHW>
__global__ __launch_bounds__(256, (CIN <= 16 ? 4 : 3)) void conv_fused_kernel(
    const float* __restrict__ in, const __half2* __restrict__ w1,
    const float* __restrict__ b1v, const __half2* __restrict__ w2,
    const float* __restrict__ b2v, float* __restrict__ out,
    const float* __restrict__ resid, int H, int W) {
    constexpr int CINP = (CIN <= 8) ? 8 : ((CIN <= 16) ? 16 : 32);
    constexpr int PAIRS = CINP / 2;
    constexpr int POP = COUT / 2;
    constexpr int NB = COUT / 8;
    constexpr int IN_W = 400 * PAIRS;
    constexpr int MID_W = (MODE == 0) ? 324 * COUT : 324 * POP;

    extern __shared__ __half2 smh[];
    __half2* s_in2 = smh;
    float* s_midf = (float*)(smh + IN_W);
    __half2* s_mid2 = smh + IN_W;
    unsigned* sm32 = (unsigned*)smh;

    const int tid = threadIdx.x;
    const int n = blockIdx.z;
    const int by = blockIdx.y * 16, bx = blockIdx.x * 16;

    for (int i = tid; i < IN_W + MID_W; i += 256) sm32[i] = 0u;
    __syncthreads();

    if (NCHW) {
        __half* s_inh = (__half*)s_in2;
        for (int i = tid; i < 400 * CIN; i += 256) {
            int ci = i / 400, pix = i - ci * 400;
            int iy = pix / 20, ix = pix - iy * 20;
            int gy = by + iy - 2, gx = bx + ix - 2;
            if (gy >= 0 && gy < H && gx >= 0 && gx < W) {
                float v = in[((long)(n * CIN + ci) * H + gy) * W + gx];
                if (RELU_IN) v = fmaxf(v, 0.0f);
                s_inh[pix * 8 + ci] = __float2half_rn(v);
            }
        }
    } else {
        constexpr int C4 = CIN / 4;
        for (int i = tid; i < 400 * C4; i += 256) {
            int pix = i / C4, c4 = i - pix * C4;
            int iy = pix / 20, ix = pix - iy * 20;
            int gy = by + iy - 2, gx = bx + ix - 2;
            if (gy >= 0 && gy < H && gx >= 0 && gx < W) {
                float4 v = *(const float4*)(in + ((long)(n * H + gy) * W + gx) * CIN + 4 * c4);
                if (RELU_IN) {
                    v.x = fmaxf(v.x, 0.0f); v.y = fmaxf(v.y, 0.0f);
                    v.z = fmaxf(v.z, 0.0f); v.w = fmaxf(v.w, 0.0f);
                }
                s_in2[pix * PAIRS + pslot(2 * c4, PAIRS)] = __floats2half2_rn(v.x, v.y);
                s_in2[pix * PAIRS + pslot(2 * c4 + 1, PAIRS)] = __floats2half2_rn(v.z, v.w);
            }
        }
    }
    __syncthreads();

    const int warp = tid >> 5, lane = tid & 31, g = lane >> 2, t = lane & 3;
    const unsigned* su = (const unsigned*)s_in2;
    const unsigned* w1u = (const unsigned*)w1;

    float acc1[3][NB][4];
#pragma unroll
    for (int s = 0; s < 3; s++)
#pragma unroll
        for (int nb = 0; nb < NB; nb++)
#pragma unroll
            for (int q = 0; q < 4; q++) acc1[s][nb][q] = 0.0f;

    int base0[3], base1[3];
#pragma unroll
    for (int s = 0; s < 3; s++) {
        int tt = warp + 8 * s;
        int p0 = tt * 16 + g, p1 = p0 + 8;
        int q0 = p0 > 323 ? 323 : p0, q1 = p1 > 323 ? 323 : p1;
        base0[s] = (q0 / 18 + 1) * 20 + (q0 % 18 + 1);
        base1[s] = (q1 / 18 + 1) * 20 + (q1 % 18 + 1);
    }

#pragma unroll
    for (int tap = 0; tap < 9; tap++) {
        const int dy = tap / 3 - 1, dx = tap % 3 - 1;
        const int off = dy * 20 + dx;
        if (PAIRS == 4) {
            unsigned vb[NB];
#pragma unroll
            for (int nb = 0; nb < NB; nb++)
                vb[nb] = w1u[(tap * COUT + nb * 8 + g) * 4 + t];
#pragma unroll
            for (int s = 0; s < 3; s++) {
                unsigned a0 = su[(base0[s] + off) * 4 + t];
                unsigned a1 = su[(base1[s] + off) * 4 + t];
#pragma unroll
                for (int nb = 0; nb < NB; nb++) mma8h(acc1[s][nb], a0, a1, vb[nb]);
            }
        } else if (PAIRS == 8) {
            uint2 vb[NB];
#pragma unroll
            for (int nb = 0; nb < NB; nb++)
                vb[nb] = *(const uint2*)(w1u + (tap * COUT + nb * 8 + g) * 8 + 2 * t);
#pragma unroll
            for (int s = 0; s < 3; s++) {
                uint2 va0 = *(const uint2*)(su + (base0[s] + off) * 8 + 2 * t);
                uint2 va1 = *(const uint2*)(su + (base1[s] + off) * 8 + 2 * t);
#pragma unroll
                for (int nb = 0; nb < NB; nb++)
                    mma16h(acc1[s][nb], va0.x, va1.x, va0.y, va1.y, vb[nb].x, vb[nb].y);
            }
        } else {
            uint4 vb[NB];
#pragma unroll
            for (int nb = 0; nb < NB; nb++)
                vb[nb] = *(const uint4*)(w1u + (tap * COUT + nb * 8 + g) * 16 + 4 * t);
#pragma unroll
            for (int s = 0; s < 3; s++) {
                uint4 va0 = *(const uint4*)(su + (base0[s] + off) * 16 + 4 * t);
                uint4 va1 = *(const uint4*)(su + (base1[s] + off) * 16 + 4 * t);
#pragma unroll
                for (int nb = 0; nb < NB; nb++) {
                    mma16h(acc1[s][nb], va0.x, va1.x, va0.y, va1.y, vb[nb].x, vb[nb].y);
                    mma16h(acc1[s][nb], va0.z, va1.z, va0.w, va1.w, vb[nb].z, vb[nb].w);
                }
            }
        }
    }

#pragma unroll
    for (int s = 0; s < 3; s++) {
        int pbase = (warp + 8 * s) * 16 + g;
#pragma unroll
        for (int half = 0; half < 2; half++) {
            int p = pbase + 8 * half;
            if (p < 324) {
                int r = p / 18, c = p - r * 18;
                int gy = by - 1 + r, gx = bx - 1 + c;
                if (gy >= 0 && gy < H && gx >= 0 && gx < W) {
#pragma unroll
                    for (int nb = 0; nb < NB; nb++) {
                        int co = nb * 8 + 2 * t;
                        float v0 = acc1[s][nb][2 * half + 0] + b1v[co];
                        float v1 = acc1[s][nb][2 * half + 1] + b1v[co + 1];
                        if (MODE == 0) {
                            s_midf[p * COUT + co] = v0;
                            s_midf[p * COUT + co + 1] = v1;
                        } else {
                            int pr = nb * 4 + t;
                            s_mid2[p * POP + pslot(pr, POP)] =
                                __floats2half2_rn(fmaxf(v0, 0.0f), fmaxf(v1, 0.0f));
                        }
                    }
                }
            }
        }
    }
    __syncthreads();

    if (MODE == 0) {
        int H2 = H >> 1, W2 = W >> 1;
        for (int o = tid; o < 64 * COUT; o += 256) {
            int co = o % COUT; int pp = o / COUT;
            int ly = pp >> 3, lx = pp & 7;
            float m = -3.4e38f;
#pragma unroll
            for (int dy = 0; dy < 3; dy++) {
                int r = 2 * ly + dy;
                int gy = by - 1 + r;
                if (gy < 0 || gy >= H) continue;
#pragma unroll
                for (int dxx = 0; dxx < 3; dxx++) {
                    int c = 2 * lx + dxx;
                    int gx = bx - 1 + c;
                    if (gx < 0 || gx >= W) continue;
                    m = fmaxf(m, s_midf[(r * 18 + c) * COUT + co]);
                }
            }
            out[(((long)n * H2 + (by / 2 + ly)) * W2 + (bx / 2 + lx)) * COUT + co] = m;
        }
    } else {
        const unsigned* mu = (const unsigned*)s_mid2;
        const unsigned* w2u = (const unsigned*)w2;
        const int wr0 = warp * 2;
        float acc[2][NB][4];
#pragma unroll
        for (int r = 0; r < 2; r++)
#pragma unroll
            for (int nb = 0; nb < NB; nb++)
#pragma unroll
                for (int q = 0; q < 4; q++) acc[r][nb][q] = 0.0f;

#pragma unroll
        for (int tap = 0; tap < 9; tap++) {
            const int dy = tap / 3 - 1, dx = tap % 3 - 1;
            if (POP == 8) {
                uint2 vb[NB];
#pragma unroll
                for (int nb = 0; nb < NB; nb++)
                    vb[nb] = *(const uint2*)(w2u + (tap * COUT + nb * 8 + g) * 8 + 2 * t);
#pragma unroll
                for (int r = 0; r < 2; r++) {
                    int prow = (wr0 + r + dy + 1) * 18 + dx + 1;
                    uint2 va0 = *(const uint2*)(mu + (prow + g) * 8 + 2 * t);
                    uint2 va1 = *(const uint2*)(mu + (prow + g + 8) * 8 + 2 * t);
#pragma unroll
                    for (int nb = 0; nb < NB; nb++)
                        mma16h(acc[r][nb], va0.x, va1.x, va0.y, va1.y, vb[nb].x, vb[nb].y);
                }
            } else {
                uint4 vb[NB];
#pragma unroll
                for (int nb = 0; nb < NB; nb++)
                    vb[nb] = *(const uint4*)(w2u + (tap * COUT + nb * 8 + g) * 16 + 4 * t);
#pragma unroll
                for (int r = 0; r < 2; r++) {
                    int prow = (wr0 + r + dy + 1) * 18 + dx + 1;
                    uint4 va0 = *(const uint4*)(mu + (prow + g) * 16 + 4 * t);
                    uint4 va1 = *(const uint4*)(mu + (prow + g + 8) * 16 + 4 * t);
#pragma unroll
                    for (int nb = 0; nb < NB; nb++) {
                        mma16h(acc[r][nb], va0.x, va1.x, va0.y, va1.y, vb[nb].x, vb[nb].y);
                        mma16h(acc[r][nb], va0.z, va1.z, va0.w, va1.w, vb[nb].z, vb[nb].w);
                    }
                }
            }
        }

#pragma unroll
        for (int r = 0; r < 2; r++) {
            int oy = by + wr0 + r;
            long rowbase = (long)(n * H + oy) * W;
#pragma unroll
            for (int nb = 0; nb < NB; nb++) {
                int co = nb * 8 + 2 * t;
                float bv0 = b2v[co], bv1 = b2v[co + 1];
                long i0 = (rowbase + bx + g) * COUT + co;
                long i1 = (rowbase + bx + g + 8) * COUT + co;
                float2 r0 = *(const float2*)(resid + i0);
                float2 r1 = *(const float2*)(resid + i1);
                float2 v0 = make_float2(acc[r][nb][0] + bv0 + r0.x, acc[r][nb][1] + bv1 + r0.y);
                float2 v1 = make_float2(acc[r][nb][2] + bv0 + r1.x, acc[r][nb][3] + bv1 + r1.y);
                if (RELU_OUT) {
                    v0.x = fmaxf(v0.x, 0.0f); v0.y = fmaxf(v0.y, 0.0f);
                    v1.x = fmaxf(v1.x, 0.0f); v1.y = fmaxf(v1.y, 0.0f);
                }
                *(float2*)(out + i0) = v0;
                *(float2*)(out + i1) = v1;
            }
        }
    }
}

// ---------------- fused CBAM: stats -> MLP -> apply -> spatial -> apply ----
__global__ __launch_bounds__(256) void cbam_fused_kernel(
    float* __restrict__ x, const float* __restrict__ fc1, const float* __restrict__ fc2,
    const float* __restrict__ spw) {
    __shared__ float s_x[256 * 36];
    __shared__ float rs[8][32], rm[8][32];
    __shared__ float s_mean[32], s_max[32], s_h[8], s_ca[32], s_sp[512], s_w[98];
    const int n = blockIdx.x, tid = threadIdx.x;

    // stage X tile (256 px x 32 ch), row stride 36 (conflict-free)
    float* gbase = x + ((long)n * 256 + tid) * 32;
#pragma unroll
    for (int c = 0; c < 32; c += 4)
        *(float4*)(s_x + tid * 36 + c) = *(const float4*)(gbase + c);
    if (tid < 98) s_w[tid] = spw[tid];
    __syncthreads();

    // per-channel mean/max
    {
        int g = tid >> 5, c = tid & 31;
        float sm = 0.0f, mx = -3.4e38f;
        for (int p = g; p < 256; p += 8) {
            float v = s_x[p * 36 + c];
            sm += v; mx = fmaxf(mx, v);
        }
        rs[g][c] = sm; rm[g][c] = mx;
    }
    __syncthreads();
    if (tid < 32) {
        float s = 0.0f, m = -3.4e38f;
        for (int q = 0; q < 8; q++) { s += rs[q][tid]; m = fmaxf(m, rm[q][tid]); }
        s_mean[tid] = s * (1.0f / 256.0f); s_max[tid] = m;
    }
    __syncthreads();
    if (tid < 8) {
        float hm = 0.0f, hx = 0.0f;
        for (int k = 0; k < 32; k++) {
            float wv = fc1[tid * 32 + k];
            hm += s_mean[k] * wv; hx += s_max[k] * wv;
        }
        s_h[tid] = fmaxf(hm, 0.0f) + fmaxf(hx, 0.0f);
    }
    __syncthreads();
    if (tid < 32) {
        float o = 0.0f;
        for (int j = 0; j < 8; j++) o += s_h[j] * fc2[tid * 8 + j];
        s_ca[tid] = sigf(o);
    }
    __syncthreads();

    // apply channel attention; spatial mean/max maps
    {
        float sum = 0.0f, mx = -3.4e38f;
#pragma unroll
        for (int c = 0; c < 32; c++) {
            float v = s_x[tid * 36 + c] * s_ca[c];
            s_x[tid * 36 + c] = v;
            sum += v; mx = fmaxf(mx, v);
        }
        s_sp[tid] = sum * (1.0f / 32.0f);
        s_sp[256 + tid] = mx;
    }
    __syncthreads();

    // 7x7 spatial attention + apply, write out
    {
        int oy = tid >> 4, ox = tid & 15;
        float a = 0.0f;
#pragma unroll
        for (int ci = 0; ci < 2; ci++)
            for (int ky = 0; ky < 7; ky++) {
                int y = oy + ky - 3;
                if (y < 0 || y >= 16) continue;
                for (int kx = 0; kx < 7; kx++) {
                    int xx = ox + kx - 3;
                    if (xx < 0 || xx >= 16) continue;
                    a = fmaf(s_sp[ci * 256 + y * 16 + xx], s_w[(ci * 7 + ky) * 7 + kx], a);
                }
            }
        float sa = sigf(a);
#pragma unroll
        for (int c = 0; c < 32; c += 4) {
            float4 v;
            v.x = s_x[tid * 36 + c] * sa;
            v.y = s_x[tid * 36 + c + 1] * sa;
            v.z = s_x[tid * 36 + c + 2] * sa;
            v.w = s_x[tid * 36 + c + 3] * sa;
            *(float4*)(gbase + c) = v;
        }
    }
}

// permute fc_w[n][c*256+p] -> g_fcwT[n][p*32+c]
__global__ void fcw_permute(const float* __restrict__ w, float* __restrict__ wt) {
    int i = blockIdx.x * 256 + threadIdx.x;
    if (i >= 256 * 8192) return;
    int n = i >> 13;
    int r = i & 8191;
    int c = r >> 8, p = r & 255;
    wt[(n << 13) + p * 32 + c] = w[i];
}

// ---------------- tf32 MMA GEMM: C[M,N] = A[M,K]@B[N,K]^T + bias ----------
// Block tile 32(M) x 64(N); 8 warps = 2x4, each M16 x N16. grid (N/64, M/32).
template <int RELU>
__global__ __launch_bounds__(256) void gemm_mma_kernel(
    const float* __restrict__ A, const float* __restrict__ B,
    const float* __restrict__ bias, float* __restrict__ C,
    int M, int N, int K) {
    __shared__ float sA[32 * 36], sB[64 * 36];
    const int tid = threadIdx.x;
    const int bm = blockIdx.y * 32, bn = blockIdx.x * 64;
    const int warp = tid >> 5, lane = tid & 31, g = lane >> 2, t = lane & 3;
    const int wm = warp >> 2, wn = warp & 3;
    const int lrA = tid >> 3, lcA = (tid & 7) * 4;
    const int lrB = tid >> 2, lcB = (tid & 3) * 8;

    float acc[2][4];
#pragma unroll
    for (int i = 0; i < 2; i++)
#pragma unroll
        for (int q = 0; q < 4; q++) acc[i][q] = 0.0f;

    for (int k0 = 0; k0 < K; k0 += 32) {
        float4 va = *(const float4*)(A + (long)(bm + lrA) * K + k0 + lcA);
        float4 vb0 = *(const float4*)(B + (long)(bn + lrB) * K + k0 + lcB);
        float4 vb1 = *(const float4*)(B + (long)(bn + lrB) * K + k0 + lcB + 4);
        float* pa = sA + lrA * 36 + lcA;
        float* pb = sB + lrB * 36 + lcB;
        pa[0] = tf32f(va.x); pa[1] = tf32f(va.y); pa[2] = tf32f(va.z); pa[3] = tf32f(va.w);
        pb[0] = tf32f(vb0.x); pb[1] = tf32f(vb0.y); pb[2] = tf32f(vb0.z); pb[3] = tf32f(vb0.w);
        pb[4] = tf32f(vb1.x); pb[5] = tf32f(vb1.y); pb[6] = tf32f(vb1.z); pb[7] = tf32f(vb1.w);
        __syncthreads();
#pragma unroll
        for (int ks = 0; ks < 4; ks++) {
            const int k = ks * 8;
            const int r0 = wm * 16 + g;
            unsigned a0 = U(sA[r0 * 36 + k + t]),       a1 = U(sA[(r0 + 8) * 36 + k + t]);
            unsigned a2 = U(sA[r0 * 36 + k + t + 4]),   a3 = U(sA[(r0 + 8) * 36 + k + t + 4]);
#pragma unroll
            for (int nt = 0; nt < 2; nt++) {
                int nr = wn * 16 + nt * 8 + g;
                mma8(acc[nt], a0, a1, a2, a3, sB[nr * 36 + k + t], sB[nr * 36 + k + t + 4]);
            }
        }
        __syncthreads();
    }
#pragma unroll
    for (int nt = 0; nt < 2; nt++) {
        int n0 = bn + wn * 16 + nt * 8 + 2 * t;
        int m0 = bm + wm * 16 + g;
        float b0 = bias[n0], b1 = bias[n0 + 1];
        float v00 = acc[nt][0] + b0, v01 = acc[nt][1] + b1;
        float v10 = acc[nt][2] + b0, v11 = acc[nt][3] + b1;
        if (RELU) {
            v00 = fmaxf(v00, 0.0f); v01 = fmaxf(v01, 0.0f);
            v10 = fmaxf(v10, 0.0f); v11 = fmaxf(v11, 0.0f);
        }
        C[(long)m0 * N + n0] = v00;       C[(long)m0 * N + n0 + 1] = v01;
        C[(long)(m0 + 8) * N + n0] = v10; C[(long)(m0 + 8) * N + n0 + 1] = v11;
    }
}

// ---------------- GRU scan (whh as fp16 pairs in smem) ----------------
__global__ void gru_scan_kernel(const float* __restrict__ gi, const float* __restrict__ done,
                                const float* __restrict__ h0, const float* __restrict__ whh,
                                const float* __restrict__ bhh, float* __restrict__ hidden) {
    extern __shared__ __half2 smg[];
    __half2* s_whh = smg;                        // [k2][j]: 64*384 half2
    float* s_gh = (float*)(smg + 64 * 384);      // 384
    float* s_h = s_gh + 384;                     // 128
    float* s_hm = s_h + 128;                     // 128
    int b = blockIdx.x, j = threadIdx.x;

    for (int i = j; i < 64 * 384; i += 384) {
        int jj = i / 64, k2 = i - jj * 64;
        s_whh[k2 * 384 + jj] = __floats2half2_rn(whh[jj * 128 + 2 * k2],
                                                 whh[jj * 128 + 2 * k2 + 1]);
    }
    if (j < 128) s_h[j] = h0[b * 128 + j];
    __syncthreads();

    float bh = bhh[j];
    for (int t = 0; t < 64; t++) {
        float dt = done[t * 8 + b];
        if (j < 128) s_hm[j] = (1.0f - dt) * s_h[j];
        __syncthreads();
        float acc = bh;
#pragma unroll 8
        for (int k2 = 0; k2 < 64; k2++) {
            float2 wv = __half22float2(s_whh[k2 * 384 + j]);
            float2 hm = *(const float2*)(s_hm + 2 * k2);
            acc = fmaf(hm.x, wv.x, acc);
            acc = fmaf(hm.y, wv.y, acc);
        }
        s_gh[j] = acc;
        __syncthreads();
        if (j < 128) {
            const float* gr = gi + (long)(t * 8 + b) * 384;
            float r = sigf(gr[j] + s_gh[j]);
            float z = sigf(gr[128 + j] + s_gh[128 + j]);
            float nn = tanhf(gr[256 + j] + r * s_gh[256 + j]);
            float hn = (1.0f - z) * nn + z * s_hm[j];
            s_h[j] = hn;
            hidden[(long)(t * 8 + b) * 128 + j] = hn;
        }
        __syncthreads();
    }
}

// ---------------- actor/critic heads ----------------
__global__ void heads_kernel(const float* __restrict__ hidden, const float* __restrict__ aw,
                             const float* __restrict__ ab, const float* __restrict__ cw,
                             const float* __restrict__ cb, float* __restrict__ out) {
    int row = blockIdx.x, t = threadIdx.x;
    __shared__ float s_h[128];
    s_h[t] = hidden[(long)row * 128 + t];
    __syncthreads();
    if (t < 4) {
        const float* w = (t < 3) ? (aw + t * 128) : cw;
        float s = (t < 3) ? ab[t] : cb[0];
        for (int k = 0; k < 128; k++) s = fmaf(s_h[k], w[k], s);
        out[row * 4 + t] = s;
    }
}

// ---------------- host-side launch helpers ----------------
template <int CIN, int COUT, bool RELU_IN, int MODE, bool RELU_OUT, bool NCHW>
static void launch_fused(const float* in, const __half2* w1, const float* b1,
                         const __half2* w2, const float* b2,
                         float* out, const float* resid, int H, int W) {
    constexpr int CINP = (CIN <= 8) ? 8 : ((CIN <= 16) ? 16 : 32);
    constexpr int PAIRS = CINP / 2;
    constexpr int MID_W = (MODE == 0) ? 324 * COUT : 324 * (COUT / 2);
    int smem = (400 * PAIRS + MID_W) * 4;
    auto kfn = conv_fused_kernel<CIN, COUT, RELU_IN, MODE, RELU_OUT, NCHW>;
    cudaFuncSetAttribute(kfn, cudaFuncAttributeMaxDynamicSharedMemorySize, smem);
    dim3 grid(W / 16, H / 16, 512);
    kfn<<<grid, 256, smem>>>(in, w1, b1, w2, b2, out, resid, H, W);
}

extern "C" void kernel_launch(void* const* d_in, const int* in_sizes, int n_in,
                              void* d_out, int out_size) {
    (void)in_sizes; (void)n_in; (void)out_size;
    const float* x        = (const float*)d_in[0];
    const float* done     = (const float*)d_in[1];
    const float* grustate = (const float*)d_in[2];
    const float* s0_cw = (const float*)d_in[3];
    const float* s0_cb = (const float*)d_in[4];
    const float* s0_rw = (const float*)d_in[5];
    const float* s0_rb = (const float*)d_in[6];
    const float* s1_cw = (const float*)d_in[7];
    const float* s1_cb = (const float*)d_in[8];
    const float* s1_rw = (const float*)d_in[9];
    const float* s1_rb = (const float*)d_in[10];
    const float* s2_cw = (const float*)d_in[11];
    const float* s2_cb = (const float*)d_in[12];
    const float* s2_rw = (const float*)d_in[13];
    const float* s2_rb = (const float*)d_in[14];
    const float* cbam_fc1 = (const float*)d_in[15];
    const float* cbam_fc2 = (const float*)d_in[16];
    const float* cbam_spw = (const float*)d_in[17];
    const float* fc_w  = (const float*)d_in[18];
    const float* fc_b  = (const float*)d_in[19];
    const float* gwih  = (const float*)d_in[20];
    const float* gwhh  = (const float*)d_in[21];
    const float* gbih  = (const float*)d_in[22];
    const float* gbhh  = (const float*)d_in[23];
    const float* aw    = (const float*)d_in[24];
    const float* ab    = (const float*)d_in[25];
    const float* cw    = (const float*)d_in[26];
    const float* cb    = (const float*)d_in[27];
    float* out = (float*)d_out;

    float *X, *O, *FEAT, *GI, *HID, *FCWT;
    __half2* WP;
    cudaGetSymbolAddress((void**)&X, g_X);
    cudaGetSymbolAddress((void**)&O, g_O);
    cudaGetSymbolAddress((void**)&FEAT, g_feat);
    cudaGetSymbolAddress((void**)&GI, g_gi);
    cudaGetSymbolAddress((void**)&HID, g_hid);
    cudaGetSymbolAddress((void**)&FCWT, g_fcwT);
    cudaGetSymbolAddress((void**)&WP, g_wperm2);

    // weight offsets in half2 units
    const int OFF_S0C = 0;
    const int OFF_S0R = 576;
    const int OFF_S1C = 5184;
    const int OFF_S1R = 7488;
    const int OFF_S2C = 25920;
    const int OFF_S2R = 30528;

    wperm_all_kernel<<<(48960 + 255) / 256, 256>>>(s0_cw, s0_rw, s1_cw, s1_rw, s2_cw, s2_rw, WP);
    fcw_permute<<<(256 * 8192 + 255) / 256, 256>>>(fc_w, FCWT);

    // ---- stage 0 ----
    launch_fused<6, 16, false, 0, false, true>(x, WP + OFF_S0C, s0_cb, WP + OFF_S0C, s0_cb, X, nullptr, 128, 128);
    launch_fused<16, 16, true, 1, false, false>(X, WP + OFF_S0R + 0 * 1152, s0_rb + 0,
                                                WP + OFF_S0R + 1 * 1152, s0_rb + 16, O, X, 64, 64);
    launch_fused<16, 16, true, 1, false, false>(O, WP + OFF_S0R + 2 * 1152, s0_rb + 32,
                                                WP + OFF_S0R + 3 * 1152, s0_rb + 48, X, O, 64, 64);

    // ---- stage 1 ----
    launch_fused<16, 32, false, 0, false, false>(X, WP + OFF_S1C, s1_cb, WP + OFF_S1C, s1_cb, O, nullptr, 64, 64);
    launch_fused<32, 32, true, 1, false, false>(O, WP + OFF_S1R + 0 * 4608, s1_rb + 0,
                                                WP + OFF_S1R + 1 * 4608, s1_rb + 32, X, O, 32, 32);
    launch_fused<32, 32, true, 1, false, false>(X, WP + OFF_S1R + 2 * 4608, s1_rb + 64,
                                                WP + OFF_S1R + 3 * 4608, s1_rb + 96, O, X, 32, 32);

    // ---- stage 2 ----
    launch_fused<32, 32, false, 0, false, false>(O, WP + OFF_S2C, s2_cb, WP + OFF_S2C, s2_cb, X, nullptr, 32, 32);
    launch_fused<32, 32, true, 1, false, false>(X, WP + OFF_S2R + 0 * 4608, s2_rb + 0,
                                                WP + OFF_S2R + 1 * 4608, s2_rb + 32, O, X, 16, 16);
    launch_fused<32, 32, true, 1, true, false>(O, WP + OFF_S2R + 2 * 4608, s2_rb + 64,
                                               WP + OFF_S2R + 3 * 4608, s2_rb + 96, X, O, 16, 16);

    // ---- fused CBAM (NHWC, on X) ----
    cbam_fused_kernel<<<512, 256>>>(X, cbam_fc1, cbam_fc2, cbam_spw);

    // ---- FC 8192->256 (+relu) and GRU input-gate GEMM ----
    gemm_mma_kernel<1><<<dim3(256 / 64, 512 / 32), 256>>>(X, FCWT, fc_b, FEAT, 512, 256, 8192);
    gemm_mma_kernel<0><<<dim3(384 / 64, 512 / 32), 256>>>(FEAT, gwih, gbih, GI, 512, 384, 256);

    // ---- GRU sequential scan ----
    {
        int smem = 64 * 384 * 4 + (384 + 128 + 128) * 4;
        cudaFuncSetAttribute(gru_scan_kernel, cudaFuncAttributeMaxDynamicSharedMemorySize, smem);
        gru_scan_kernel<<<8, 384, smem>>>(GI, done, grustate, gwhh, gbhh, HID);
    }

    // ---- actor / critic heads -> (512, 4) ----
    heads_kernel<<<512, 128>>>(HID, aw, ab, cw, cb, out);
}